// round 1
// baseline (speedup 1.0000x reference)
#include <cuda_runtime.h>
#include <cuda_bf16.h>
#include <cstdint>

// ---------------- problem constants ----------------
#define BATCH 16
#define TLEN  4095
#define LSEQ  4096          // TLEN + 1
#define NTOK  (BATCH*LSEQ)  // 65536
#define OBSD  128
#define HID   256
#define NHEAD 8
#define DHEAD 32
#define FFD   1024
#define NLAY  4
#define KEPS  1e-3f
#define LNEPS 1e-6f

// ---------------- device scratch (allocation-free rule: __device__ globals) ----
__device__ float g_x   [(size_t)NTOK*HID];
__device__ float g_qp  [(size_t)NTOK*HID];   // qp, later reused as o / z
__device__ float g_kp  [(size_t)NTOK*HID];
__device__ float g_v   [(size_t)NTOK*HID];
__device__ float g_attn[(size_t)NTOK*HID];
__device__ float g_ffn [(size_t)NTOK*FFD];
__device__ float g_kv  [BATCH*NHEAD*DHEAD*DHEAD];
__device__ float g_ksum[BATCH*NHEAD*DHEAD];

static inline int cdiv(int a, int b) { return (a + b - 1) / b; }

// ---------------- hidden-state init: x[b,0,:] = resets[b] ? 0 : hidden ----------
__global__ void ta_init_hidden(const float* __restrict__ hs,
                               const unsigned char* __restrict__ resets,
                               float* __restrict__ X) {
    int b = blockIdx.x, c = threadIdx.x;
    float v = resets[b] ? 0.f : hs[b*HID + c];
    X[(size_t)b*LSEQ*HID + c] = v;
}

// ---------------- SGEMM 128x128x8, 256 threads, TM=TN=8 ----------------
// C[M,Nc] = A[M,K] @ W[K,Nc] + bias ; epi: 0=none, 1=relu+KEPS, 2=relu
// embRemap: output row r -> (r/TLEN)*LSEQ + 1 + r%TLEN
__global__ __launch_bounds__(256, 2)
void ta_sgemm(const float* __restrict__ A, const float* __restrict__ W,
              const float* __restrict__ bias, float* __restrict__ C,
              int M, int K, int Nc, int epi, int embRemap) {
    __shared__ float As[8][128];
    __shared__ float Bs[8][128];
    const int tid = threadIdx.x;
    const int rowBase = blockIdx.y * 128;
    const int colBase = blockIdx.x * 128;
    const int tr = (tid >> 4) << 3;   // 0..120
    const int tc = (tid & 15) << 3;   // 0..120
    const int aRow = tid >> 1, aCol = (tid & 1) << 2;
    const int bRow = tid >> 5, bCol = (tid & 31) << 2;

    const bool aval = (rowBase + aRow) < M;
    const float* Aptr = A + (size_t)(rowBase + aRow) * K + aCol;
    const float* Wptr = W + (size_t)bRow * Nc + colBase + bCol;

    float acc[8][8] = {};

    for (int k0 = 0; k0 < K; k0 += 8) {
        float4 av = aval ? *(const float4*)(Aptr + k0) : make_float4(0.f,0.f,0.f,0.f);
        As[aCol+0][aRow] = av.x; As[aCol+1][aRow] = av.y;
        As[aCol+2][aRow] = av.z; As[aCol+3][aRow] = av.w;
        *(float4*)&Bs[bRow][bCol] = *(const float4*)(Wptr + (size_t)k0 * Nc);
        __syncthreads();
        #pragma unroll
        for (int k = 0; k < 8; k++) {
            float4 a0 = *(const float4*)&As[k][tr];
            float4 a1 = *(const float4*)&As[k][tr+4];
            float4 b0 = *(const float4*)&Bs[k][tc];
            float4 b1 = *(const float4*)&Bs[k][tc+4];
            float ra[8] = {a0.x,a0.y,a0.z,a0.w,a1.x,a1.y,a1.z,a1.w};
            float rb[8] = {b0.x,b0.y,b0.z,b0.w,b1.x,b1.y,b1.z,b1.w};
            #pragma unroll
            for (int i = 0; i < 8; i++)
                #pragma unroll
                for (int j = 0; j < 8; j++)
                    acc[i][j] += ra[i] * rb[j];
        }
        __syncthreads();
    }

    float bb[8];
    #pragma unroll
    for (int j = 0; j < 8; j++) bb[j] = bias[colBase + tc + j];

    #pragma unroll
    for (int i = 0; i < 8; i++) {
        int row = rowBase + tr + i;
        if (row >= M) continue;
        size_t orow = row;
        if (embRemap) {
            int b = row / TLEN;
            int t = row - b * TLEN;
            orow = (size_t)b * LSEQ + 1 + t;
        }
        float* crow = C + orow * Nc + colBase + tc;
        #pragma unroll
        for (int j = 0; j < 8; j++) {
            float vv = acc[i][j] + bb[j];
            if (epi == 1) vv = fmaxf(vv, 0.f) + KEPS;
            else if (epi == 2) vv = fmaxf(vv, 0.f);
            crow[j] = vv;
        }
    }
}

// ---------------- zero kv/ksum ----------------
__global__ void ta_zero_kv(float* __restrict__ KV, float* __restrict__ KS) {
    int i = blockIdx.x * 256 + threadIdx.x;
    if (i < BATCH*NHEAD*DHEAD*DHEAD) KV[i] = 0.f;
    if (i < BATCH*NHEAD*DHEAD)       KS[i] = 0.f;
}

// ---------------- kv = sum_l kp (x) v ; ksum = sum_l kp ----------------
// grid: (SPLIT=8, NHEAD, BATCH), block 256
__global__ void ta_kv_reduce(const float* __restrict__ KP, const float* __restrict__ V,
                             float* __restrict__ KV, float* __restrict__ KS) {
    const int s = blockIdx.x, h = blockIdx.y, b = blockIdx.z;
    const int CH = LSEQ / 8;    // 512
    const int tid = threadIdx.x;
    const int w = tid >> 5, lane = tid & 31;

    __shared__ float kps[8][32];
    __shared__ float vs [8][32];

    float acc[4] = {0.f, 0.f, 0.f, 0.f};
    float ksa = 0.f;
    const size_t rowBase = (size_t)b * LSEQ + (size_t)s * CH;

    for (int l0 = 0; l0 < CH; l0 += 8) {
        size_t r = (rowBase + l0 + w) * HID + h * DHEAD + lane;
        kps[w][lane] = KP[r];
        vs [w][lane] = V [r];
        __syncthreads();
        #pragma unroll
        for (int q = 0; q < 8; q++) {
            float vd = vs[q][lane];
            #pragma unroll
            for (int j = 0; j < 4; j++)
                acc[j] += kps[q][w + 8*j] * vd;
            if (tid < 32) ksa += kps[q][lane];
        }
        __syncthreads();
    }
    const int bh = b * NHEAD + h;
    #pragma unroll
    for (int j = 0; j < 4; j++)
        atomicAdd(&KV[bh*1024 + (w + 8*j)*32 + lane], acc[j]);
    if (tid < 32) atomicAdd(&KS[bh*32 + lane], ksa);
}

// ---------------- a = (qp @ kv) / (qp . ksum) ----------------
// grid: (LSEQ/32, BATCH), block 256. warp w -> tokens base+4w..+3, lane: h=lane/4, tk=lane%4
__global__ void ta_attn_apply(const float* __restrict__ QP,
                              const float* __restrict__ KV,
                              const float* __restrict__ KS,
                              float* __restrict__ Aout) {
    __shared__ float kvs[8 * 1028];   // per-head stride 1028 avoids bank conflicts
    __shared__ float kss[8 * 32];

    const int b = blockIdx.y;
    const int tokBase = blockIdx.x * 32;
    const int tid = threadIdx.x;

    for (int i = tid; i < 8 * 1024; i += 256) {
        int h = i >> 10, r = i & 1023;
        kvs[h * 1028 + r] = KV[(b*NHEAD + h)*1024 + r];
    }
    kss[tid] = KS[b * (NHEAD*DHEAD) + tid];
    __syncthreads();

    const int w = tid >> 5, lane = tid & 31;
    const int h = lane >> 2, tk = lane & 3;
    const int tok = tokBase + w * 4 + tk;
    const size_t row = ((size_t)b * LSEQ + tok) * HID + h * DHEAD;

    float qv[32];
    float den = 0.f;
    #pragma unroll
    for (int m = 0; m < 32; m++) {
        qv[m] = QP[row + m];
        den += qv[m] * kss[h*32 + m];
    }
    const float inv = 1.f / den;
    const float* kvh = &kvs[h * 1028];
    #pragma unroll
    for (int d = 0; d < 32; d++) {
        float sacc = 0.f;
        #pragma unroll
        for (int m = 0; m < 32; m++)
            sacc += qv[m] * kvh[m*32 + d];
        Aout[row + d] = sacc * inv;
    }
}

// ---------------- layernorm of (2*z): X = LN(2z)*scale + bias ----------------
// blockDim (32,8): one warp per row
__global__ void ta_ln2(const float* __restrict__ Z,
                       const float* __restrict__ sc, const float* __restrict__ bi,
                       float* __restrict__ X) {
    const int row  = blockIdx.x * 8 + threadIdx.y;
    const int lane = threadIdx.x;
    const float* z = Z + (size_t)row * HID;

    float v[8];
    float sum = 0.f;
    #pragma unroll
    for (int j = 0; j < 8; j++) { v[j] = 2.f * z[lane + j*32]; sum += v[j]; }
    #pragma unroll
    for (int o = 16; o; o >>= 1) sum += __shfl_xor_sync(0xffffffffu, sum, o);
    const float mean = sum * (1.f / HID);

    float vs = 0.f;
    #pragma unroll
    for (int j = 0; j < 8; j++) { float d = v[j] - mean; vs += d * d; }
    #pragma unroll
    for (int o = 16; o; o >>= 1) vs += __shfl_xor_sync(0xffffffffu, vs, o);
    const float r = rsqrtf(vs * (1.f / HID) + LNEPS);

    float* xo = X + (size_t)row * HID;
    #pragma unroll
    for (int j = 0; j < 8; j++) {
        int c = lane + j*32;
        xo[c] = (v[j] - mean) * r * sc[c] + bi[c];
    }
}

// ---------------- final readout: new_hidden + q_vals ----------------
__global__ void ta_final(const float* __restrict__ X,
                         const float* __restrict__ qpW, const float* __restrict__ qpb,
                         float* __restrict__ out) {
    const int tid = threadIdx.x;   // 512
    for (int i = tid; i < BATCH*HID; i += 512) {
        int b = i >> 8, c = i & 255;
        out[i] = X[(size_t)b * LSEQ * HID + c];
    }
    const int b = tid >> 5, j = tid & 31;
    const float* xr = &X[(size_t)b * LSEQ * HID];
    float s = qpb[j];
    #pragma unroll 8
    for (int c = 0; c < HID; c++) s += xr[c] * qpW[c*32 + j];
    out[BATCH*HID + tid] = s;
}

// ---------------- launcher ----------------
extern "C" void kernel_launch(void* const* d_in, const int* in_sizes, int n_in,
                              void* d_out, int out_size) {
    const float* hidden = (const float*)d_in[0];
    const float* ins    = (const float*)d_in[1];
    const unsigned char* resets = (const unsigned char*)d_in[2];
    const float* embW = (const float*)d_in[3];
    const float* embb = (const float*)d_in[4];
    const float* Wq = (const float*)d_in[5];
    const float* bq = (const float*)d_in[6];
    const float* Wk = (const float*)d_in[7];
    const float* bk = (const float*)d_in[8];
    const float* Wv = (const float*)d_in[9];
    const float* bv = (const float*)d_in[10];
    const float* Wo = (const float*)d_in[11];
    const float* bo = (const float*)d_in[12];
    const float* ln1s = (const float*)d_in[13];
    const float* ln1b = (const float*)d_in[14];
    const float* W1 = (const float*)d_in[15];
    const float* b1 = (const float*)d_in[16];
    const float* W2 = (const float*)d_in[17];
    const float* b2 = (const float*)d_in[18];
    const float* ln2s = (const float*)d_in[19];
    const float* ln2b = (const float*)d_in[20];
    const float* qpW = (const float*)d_in[21];
    const float* qpb = (const float*)d_in[22];

    float *x, *qp, *kp, *v, *attn, *ffn, *kv, *ks;
    cudaGetSymbolAddress((void**)&x,    g_x);
    cudaGetSymbolAddress((void**)&qp,   g_qp);
    cudaGetSymbolAddress((void**)&kp,   g_kp);
    cudaGetSymbolAddress((void**)&v,    g_v);
    cudaGetSymbolAddress((void**)&attn, g_attn);
    cudaGetSymbolAddress((void**)&ffn,  g_ffn);
    cudaGetSymbolAddress((void**)&kv,   g_kv);
    cudaGetSymbolAddress((void**)&ks,   g_ksum);

    // x[b,0,:] init + embedding GEMM into x[b,1..,:]
    ta_init_hidden<<<BATCH, HID>>>(hidden, resets, x);
    {
        int M = BATCH * TLEN;  // 65520
        ta_sgemm<<<dim3(HID/128, cdiv(M,128)), 256>>>(ins, embW, embb, x, M, OBSD, HID, 0, 1);
    }

    const dim3 g256(HID/128, NTOK/128);   // (2, 512)
    const dim3 gff (FFD/128, NTOK/128);   // (8, 512)

    for (int l = 0; l < NLAY; l++) {
        const float* Wq_l = Wq + (size_t)l*HID*HID;
        const float* Wk_l = Wk + (size_t)l*HID*HID;
        const float* Wv_l = Wv + (size_t)l*HID*HID;
        const float* Wo_l = Wo + (size_t)l*HID*HID;
        const float* W1_l = W1 + (size_t)l*HID*FFD;
        const float* W2_l = W2 + (size_t)l*FFD*HID;

        ta_sgemm<<<g256, 256>>>(x, Wq_l, bq + l*HID, qp, NTOK, HID, HID, 1, 0);
        ta_sgemm<<<g256, 256>>>(x, Wk_l, bk + l*HID, kp, NTOK, HID, HID, 1, 0);
        ta_sgemm<<<g256, 256>>>(x, Wv_l, bv + l*HID, v,  NTOK, HID, HID, 0, 0);

        ta_zero_kv<<<cdiv(BATCH*NHEAD*DHEAD*DHEAD, 256), 256>>>(kv, ks);
        ta_kv_reduce<<<dim3(8, NHEAD, BATCH), 256>>>(kp, v, kv, ks);
        ta_attn_apply<<<dim3(LSEQ/32, BATCH), 256>>>(qp, kv, ks, attn);

        ta_sgemm<<<g256, 256>>>(attn, Wo_l, bo + l*HID, qp, NTOK, HID, HID, 0, 0); // o -> qp
        ta_ln2<<<NTOK/8, dim3(32,8)>>>(qp, ln1s + l*HID, ln1b + l*HID, x);

        ta_sgemm<<<gff, 256>>>(x, W1_l, b1 + l*FFD, ffn, NTOK, HID, FFD, 2, 0);   // relu
        ta_sgemm<<<g256, 256>>>(ffn, W2_l, b2 + l*HID, qp, NTOK, FFD, HID, 0, 0); // z -> qp
        ta_ln2<<<NTOK/8, dim3(32,8)>>>(qp, ln2s + l*HID, ln2b + l*HID, x);
    }

    ta_final<<<1, 512>>>(x, qpW, qpb, (float*)d_out);
}

// round 3
// speedup vs baseline: 1.9124x; 1.9124x over previous
#include <cuda_runtime.h>
#include <cuda_bf16.h>
#include <cstdint>

// ---------------- problem constants ----------------
#define BATCH 16
#define TLEN  4095
#define LSEQ  4096          // TLEN + 1
#define NTOK  (BATCH*LSEQ)  // 65536
#define OBSD  128
#define HID   256
#define NHEAD 8
#define DHEAD 32
#define FFD   1024
#define NLAY  4
#define KEPS  1e-3f
#define LNEPS 1e-6f

typedef __nv_bfloat16 bf16;

// ---------------- device scratch: activations as bf16 hi/lo pairs ----------------
__device__ bf16 g_xh [(size_t)NTOK*HID];   __device__ bf16 g_xl [(size_t)NTOK*HID];
__device__ bf16 g_qph[(size_t)NTOK*HID];   __device__ bf16 g_qpl[(size_t)NTOK*HID];
__device__ bf16 g_kph[(size_t)NTOK*HID];   __device__ bf16 g_kpl[(size_t)NTOK*HID];
__device__ bf16 g_vh [(size_t)NTOK*HID];   __device__ bf16 g_vl [(size_t)NTOK*HID];
__device__ bf16 g_ah [(size_t)NTOK*HID];   __device__ bf16 g_al [(size_t)NTOK*HID];
__device__ bf16 g_fh [(size_t)NTOK*FFD];   __device__ bf16 g_fl [(size_t)NTOK*FFD];
__device__ bf16 g_insh[(size_t)(BATCH*TLEN)*OBSD];
__device__ bf16 g_insl[(size_t)(BATCH*TLEN)*OBSD];
__device__ float g_kv  [BATCH*NHEAD*DHEAD*DHEAD];
__device__ float g_ksum[BATCH*NHEAD*DHEAD];

// transposed bf16 hi/lo weights (WT[N][K] layout)
#define WT_EMB_SZ   (HID*OBSD)
#define WT_LAYER_SZ (4*HID*HID + 2*HID*FFD)
#define WT_TOTAL    (WT_EMB_SZ + NLAY*WT_LAYER_SZ)
__device__ bf16 g_wth[WT_TOTAL];
__device__ bf16 g_wtl[WT_TOTAL];

static inline int cdiv(int a, int b) { return (a + b - 1) / b; }

// ---------------- helpers ----------------
__device__ __forceinline__ uint32_t smem_u32(const void* p) {
    uint32_t a;
    asm("{ .reg .u64 t; cvta.to.shared.u64 t, %1; cvt.u32.u64 %0, t; }" : "=r"(a) : "l"(p));
    return a;
}
__device__ __forceinline__ float hl(const bf16* H, const bf16* L, size_t i) {
    return __bfloat162float(H[i]) + __bfloat162float(L[i]);
}
__device__ __forceinline__ void sphl(float f, bf16* H, bf16* L, size_t i) {
    bf16 h = __float2bfloat16(f);
    H[i] = h;
    L[i] = __float2bfloat16(f - __bfloat162float(h));
}

#define LDSM4(r, addr)                                                     \
    asm volatile("ldmatrix.sync.aligned.m8n8.x4.shared.b16 "               \
                 "{%0,%1,%2,%3}, [%4];"                                    \
                 : "=r"((r)[0]), "=r"((r)[1]), "=r"((r)[2]), "=r"((r)[3])  \
                 : "r"(addr))

#define MMA_BF16(d, a, b0, b1)                                             \
    asm volatile("mma.sync.aligned.m16n8k16.row.col.f32.bf16.bf16.f32 "    \
                 "{%0,%1,%2,%3},{%4,%5,%6,%7},{%8,%9},{%0,%1,%2,%3};"      \
                 : "+f"((d)[0]), "+f"((d)[1]), "+f"((d)[2]), "+f"((d)[3])  \
                 : "r"((a)[0]), "r"((a)[1]), "r"((a)[2]), "r"((a)[3]),     \
                   "r"(b0), "r"(b1))

__device__ __forceinline__ void cpa16(uint32_t dst, const void* src, int sz) {
    asm volatile("cp.async.cg.shared.global [%0], [%1], 16, %2;"
                 :: "r"(dst), "l"(__cvta_generic_to_global(src)), "r"(sz));
}

// ---------------- input conversions ----------------
__global__ void ta_split(const float* __restrict__ src,
                         bf16* __restrict__ H, bf16* __restrict__ L, int n) {
    int i = blockIdx.x * 256 + threadIdx.x;
    if (i < n) sphl(src[i], H, L, i);
}

// W[K,N] fp32 -> WT[N,K] bf16 hi/lo
__global__ void ta_wconv(const float* __restrict__ W, int K, int N,
                         bf16* __restrict__ hi, bf16* __restrict__ lo) {
    int i = blockIdx.x * 256 + threadIdx.x;
    if (i >= N * K) return;
    int n = i / K, k = i - n * K;
    float w = W[(size_t)k * N + n];
    bf16 h = __float2bfloat16(w);
    hi[i] = h;
    lo[i] = __float2bfloat16(w - __bfloat162float(h));
}

// x[b,0,:] = resets[b] ? 0 : hidden
__global__ void ta_init_hidden(const float* __restrict__ hs,
                               const unsigned char* __restrict__ resets,
                               bf16* __restrict__ XH, bf16* __restrict__ XL) {
    int b = blockIdx.x, c = threadIdx.x;
    float v = resets[b] ? 0.f : hs[b*HID + c];
    sphl(v, XH, XL, (size_t)b*LSEQ*HID + c);
}

// ---------------- bf16 hi/lo 3-pass MMA GEMM ----------------
// C = A @ B^T + bias, A[M,K]=(Ah+Al), B^T given as WT[N][K]=(Bh+Bl), all bf16.
// Passes: Ah*Bh + Ah*Bl + Al*Bh (fp32 accumulate). Outputs split hi/lo bf16.
// epi: 0 none, 1 relu+KEPS, 2 relu. embRemap: out row r -> (r/TLEN)*LSEQ+1+r%TLEN
// CTA tile 128x128, Kc=32, 8 warps (2x4), warp tile 64x32.
// smem per stage: Ah,Al,Bh,Bl each 128 rows x 40 bf16 (pad) = 10240B -> 40960B; 2 stages.
__global__ __launch_bounds__(256, 2)
void ta_gemm_bf16(const bf16* __restrict__ Ah, const bf16* __restrict__ Al,
                  const bf16* __restrict__ Bh, const bf16* __restrict__ Bl,
                  const float* __restrict__ bias,
                  bf16* __restrict__ Ch, bf16* __restrict__ Cl,
                  int M, int K, int N, int epi, int embRemap) {
    extern __shared__ char smem[];
    const uint32_t smu = smem_u32(smem);

    const int tid  = threadIdx.x;
    const int wid  = tid >> 5;
    const int lane = tid & 31;
    const int wr   = wid >> 2;       // 0..1 (row 64-blocks)
    const int wc   = wid & 3;        // 0..3 (col 32-blocks)
    const int rowBase = blockIdx.y * 128;
    const int colBase = blockIdx.x * 128;

    // cp.async mapping: thread -> (row r, 16B chunk ch), handles rows r and r+64
    const int r  = tid >> 2;
    const int ch = tid & 3;

    // ldmatrix lane offset within a 16-row x 16-col bf16 block (pad-40 rows)
    const uint32_t laneOff = (uint32_t)(((lane & 15) * 40 + ((lane >> 4) << 3)) * 2);
    const uint32_t aWarp = (uint32_t)(wr * 64 * 80);
    const uint32_t bWarp = (uint32_t)(wc * 32 * 80);

    float acc[4][4][4] = {};

    auto load_stage = [&](int st, int kt) {
        const uint32_t sb = smu + st * 40960u;
        const int kOff = kt * 32;
        #pragma unroll
        for (int hf = 0; hf < 2; hf++) {
            const int rr = r + hf * 64;
            // A (M-guarded)
            const int grow = rowBase + rr;
            const int sz = (grow < M) ? 16 : 0;
            const size_t asrc = (size_t)(sz ? grow : 0) * K + kOff + ch * 8;
            const uint32_t dA = sb + rr * 80 + ch * 16;
            cpa16(dA,          Ah + asrc, sz);
            cpa16(dA + 10240u, Al + asrc, sz);
            // B (always full)
            const size_t bsrc = (size_t)(colBase + rr) * K + kOff + ch * 8;
            const uint32_t dB = sb + 20480u + rr * 80 + ch * 16;
            cpa16(dB,          Bh + bsrc, 16);
            cpa16(dB + 10240u, Bl + bsrc, 16);
        }
        asm volatile("cp.async.commit_group;");
    };

    auto compute = [&](int st) {
        const uint32_t sb = smu + st * 40960u;
        #pragma unroll
        for (int pass = 0; pass < 3; pass++) {
            const uint32_t aB = sb + (pass == 2 ? 10240u : 0u) + aWarp + laneOff;
            const uint32_t bB = sb + 20480u + (pass == 1 ? 10240u : 0u) + bWarp + laneOff;
            #pragma unroll
            for (int ks = 0; ks < 2; ks++) {
                uint32_t a[4][4], bb[2][4];
                #pragma unroll
                for (int mi = 0; mi < 4; mi++) LDSM4(a[mi], aB + mi * 1280u + ks * 32u);
                #pragma unroll
                for (int nj = 0; nj < 2; nj++) LDSM4(bb[nj], bB + nj * 1280u + ks * 32u);
                #pragma unroll
                for (int mi = 0; mi < 4; mi++)
                    #pragma unroll
                    for (int nt = 0; nt < 4; nt++)
                        MMA_BF16(acc[mi][nt], a[mi], bb[nt >> 1][nt & 1], bb[nt >> 1][(nt & 1) + 2]);
            }
        }
    };

    const int nk = K >> 5;
    load_stage(0, 0);
    for (int kt = 0; kt < nk; kt++) {
        if (kt + 1 < nk) {
            load_stage((kt + 1) & 1, kt + 1);
        } else {
            asm volatile("cp.async.commit_group;");
        }
        asm volatile("cp.async.wait_group 1;");
        __syncthreads();
        compute(kt & 1);
        __syncthreads();
    }

    // ---- epilogue: bias + activation, split hi/lo, store
    const int t4 = lane >> 2;
    const int t2 = (lane & 3) << 1;
    #pragma unroll
    for (int mi = 0; mi < 4; mi++) {
        #pragma unroll
        for (int duo = 0; duo < 2; duo++) {
            const int row = rowBase + wr * 64 + mi * 16 + t4 + duo * 8;
            if (row >= M) continue;
            size_t orow = (size_t)row;
            if (embRemap) {
                int b = row / TLEN;
                orow = (size_t)b * LSEQ + 1 + (row - b * TLEN);
            }
            #pragma unroll
            for (int nt = 0; nt < 4; nt++) {
                const int col = colBase + wc * 32 + nt * 8 + t2;
                float c0 = acc[mi][nt][duo * 2 + 0] + bias[col];
                float c1 = acc[mi][nt][duo * 2 + 1] + bias[col + 1];
                if (epi == 1)      { c0 = fmaxf(c0, 0.f) + KEPS; c1 = fmaxf(c1, 0.f) + KEPS; }
                else if (epi == 2) { c0 = fmaxf(c0, 0.f);        c1 = fmaxf(c1, 0.f); }
                bf16 h0 = __float2bfloat16(c0), h1 = __float2bfloat16(c1);
                bf16 l0 = __float2bfloat16(c0 - __bfloat162float(h0));
                bf16 l1 = __float2bfloat16(c1 - __bfloat162float(h1));
                uint32_t hp = (uint32_t)*(uint16_t*)&h0 | ((uint32_t)*(uint16_t*)&h1 << 16);
                uint32_t lp = (uint32_t)*(uint16_t*)&l0 | ((uint32_t)*(uint16_t*)&l1 << 16);
                *(uint32_t*)(Ch + orow * N + col) = hp;
                *(uint32_t*)(Cl + orow * N + col) = lp;
            }
        }
    }
}

// ---------------- zero kv/ksum ----------------
__global__ void ta_zero_kv(float* __restrict__ KV, float* __restrict__ KS) {
    int i = blockIdx.x * 256 + threadIdx.x;
    if (i < BATCH*NHEAD*DHEAD*DHEAD) KV[i] = 0.f;
    if (i < BATCH*NHEAD*DHEAD)       KS[i] = 0.f;
}

// ---------------- kv = sum_l kp (x) v ; ksum = sum_l kp ----------------
__global__ void ta_kv_reduce(const bf16* __restrict__ KPh, const bf16* __restrict__ KPl,
                             const bf16* __restrict__ Vh,  const bf16* __restrict__ Vl,
                             float* __restrict__ KV, float* __restrict__ KS) {
    const int s = blockIdx.x, h = blockIdx.y, b = blockIdx.z;
    const int CH = LSEQ / 8;
    const int tid = threadIdx.x;
    const int w = tid >> 5, lane = tid & 31;

    __shared__ float kps[8][32];
    __shared__ float vs [8][32];

    float acc[4] = {0.f, 0.f, 0.f, 0.f};
    float ksa = 0.f;
    const size_t rowBase = (size_t)b * LSEQ + (size_t)s * CH;

    for (int l0 = 0; l0 < CH; l0 += 8) {
        size_t rr = (rowBase + l0 + w) * HID + h * DHEAD + lane;
        kps[w][lane] = hl(KPh, KPl, rr);
        vs [w][lane] = hl(Vh,  Vl,  rr);
        __syncthreads();
        #pragma unroll
        for (int q = 0; q < 8; q++) {
            float vd = vs[q][lane];
            #pragma unroll
            for (int j = 0; j < 4; j++)
                acc[j] += kps[q][w + 8*j] * vd;
            if (tid < 32) ksa += kps[q][lane];
        }
        __syncthreads();
    }
    const int bh = b * NHEAD + h;
    #pragma unroll
    for (int j = 0; j < 4; j++)
        atomicAdd(&KV[bh*1024 + (w + 8*j)*32 + lane], acc[j]);
    if (tid < 32) atomicAdd(&KS[bh*32 + lane], ksa);
}

// ---------------- a = (qp @ kv) / (qp . ksum) ----------------
__global__ void ta_attn_apply(const bf16* __restrict__ QPh, const bf16* __restrict__ QPl,
                              const float* __restrict__ KV, const float* __restrict__ KS,
                              bf16* __restrict__ AH, bf16* __restrict__ AL) {
    __shared__ float kvs[8 * 1028];
    __shared__ float kss[8 * 32];

    const int b = blockIdx.y;
    const int tokBase = blockIdx.x * 32;
    const int tid = threadIdx.x;

    for (int i = tid; i < 8 * 1024; i += 256) {
        int h = i >> 10, rr = i & 1023;
        kvs[h * 1028 + rr] = KV[(b*NHEAD + h)*1024 + rr];
    }
    kss[tid] = KS[b * (NHEAD*DHEAD) + tid];
    __syncthreads();

    const int w = tid >> 5, lane = tid & 31;
    const int h = lane >> 2, tk = lane & 3;
    const int tok = tokBase + w * 4 + tk;
    const size_t row = ((size_t)b * LSEQ + tok) * HID + h * DHEAD;

    float qv[32];
    float den = 0.f;
    #pragma unroll
    for (int m = 0; m < 32; m++) {
        qv[m] = hl(QPh, QPl, row + m);
        den += qv[m] * kss[h*32 + m];
    }
    const float inv = 1.f / den;
    const float* kvh = &kvs[h * 1028];
    #pragma unroll
    for (int d = 0; d < 32; d++) {
        float sacc = 0.f;
        #pragma unroll
        for (int m = 0; m < 32; m++)
            sacc += qv[m] * kvh[m*32 + d];
        sphl(sacc * inv, AH, AL, row + d);
    }
}

// ---------------- X = LN(2*Z)*scale + bias ----------------
__global__ void ta_ln2(const bf16* __restrict__ ZH, const bf16* __restrict__ ZL,
                       const float* __restrict__ sc, const float* __restrict__ bi,
                       bf16* __restrict__ XH, bf16* __restrict__ XL) {
    const int row  = blockIdx.x * 8 + threadIdx.y;
    const int lane = threadIdx.x;
    const size_t base = (size_t)row * HID;

    float v[8];
    float sum = 0.f;
    #pragma unroll
    for (int j = 0; j < 8; j++) { v[j] = 2.f * hl(ZH, ZL, base + lane + j*32); sum += v[j]; }
    #pragma unroll
    for (int o = 16; o; o >>= 1) sum += __shfl_xor_sync(0xffffffffu, sum, o);
    const float mean = sum * (1.f / HID);

    float vs = 0.f;
    #pragma unroll
    for (int j = 0; j < 8; j++) { float d = v[j] - mean; vs += d * d; }
    #pragma unroll
    for (int o = 16; o; o >>= 1) vs += __shfl_xor_sync(0xffffffffu, vs, o);
    const float rr = rsqrtf(vs * (1.f / HID) + LNEPS);

    #pragma unroll
    for (int j = 0; j < 8; j++) {
        int c = lane + j*32;
        sphl((v[j] - mean) * rr * sc[c] + bi[c], XH, XL, base + c);
    }
}

// ---------------- final readout ----------------
__global__ void ta_final(const bf16* __restrict__ XH, const bf16* __restrict__ XL,
                         const float* __restrict__ qpW, const float* __restrict__ qpb,
                         float* __restrict__ out) {
    const int tid = threadIdx.x;   // 512
    for (int i = tid; i < BATCH*HID; i += 512) {
        int b = i >> 8, c = i & 255;
        out[i] = hl(XH, XL, (size_t)b * LSEQ * HID + c);
    }
    const int b = tid >> 5, j = tid & 31;
    const size_t xr = (size_t)b * LSEQ * HID;
    float s = qpb[j];
    #pragma unroll 8
    for (int c = 0; c < HID; c++) s += hl(XH, XL, xr + c) * qpW[c*32 + j];
    out[BATCH*HID + tid] = s;
}

// ---------------- launcher ----------------
extern "C" void kernel_launch(void* const* d_in, const int* in_sizes, int n_in,
                              void* d_out, int out_size) {
    const float* hidden = (const float*)d_in[0];
    const float* ins    = (const float*)d_in[1];
    const unsigned char* resets = (const unsigned char*)d_in[2];
    const float* embW = (const float*)d_in[3];
    const float* embb = (const float*)d_in[4];
    const float* Wq = (const float*)d_in[5];
    const float* bq = (const float*)d_in[6];
    const float* Wk = (const float*)d_in[7];
    const float* bk = (const float*)d_in[8];
    const float* Wv = (const float*)d_in[9];
    const float* bv = (const float*)d_in[10];
    const float* Wo = (const float*)d_in[11];
    const float* bo = (const float*)d_in[12];
    const float* ln1s = (const float*)d_in[13];
    const float* ln1b = (const float*)d_in[14];
    const float* W1 = (const float*)d_in[15];
    const float* b1 = (const float*)d_in[16];
    const float* W2 = (const float*)d_in[17];
    const float* b2 = (const float*)d_in[18];
    const float* ln2s = (const float*)d_in[19];
    const float* ln2b = (const float*)d_in[20];
    const float* qpW = (const float*)d_in[21];
    const float* qpb = (const float*)d_in[22];

    bf16 *xh,*xl,*qph,*qpl,*kph,*kpl,*vh,*vl,*ah,*al,*fh,*fl,*insh,*insl,*wth,*wtl;
    float *kv, *ks;
    cudaGetSymbolAddress((void**)&xh,  g_xh);  cudaGetSymbolAddress((void**)&xl,  g_xl);
    cudaGetSymbolAddress((void**)&qph, g_qph); cudaGetSymbolAddress((void**)&qpl, g_qpl);
    cudaGetSymbolAddress((void**)&kph, g_kph); cudaGetSymbolAddress((void**)&kpl, g_kpl);
    cudaGetSymbolAddress((void**)&vh,  g_vh);  cudaGetSymbolAddress((void**)&vl,  g_vl);
    cudaGetSymbolAddress((void**)&ah,  g_ah);  cudaGetSymbolAddress((void**)&al,  g_al);
    cudaGetSymbolAddress((void**)&fh,  g_fh);  cudaGetSymbolAddress((void**)&fl,  g_fl);
    cudaGetSymbolAddress((void**)&insh,g_insh);cudaGetSymbolAddress((void**)&insl,g_insl);
    cudaGetSymbolAddress((void**)&wth, g_wth); cudaGetSymbolAddress((void**)&wtl, g_wtl);
    cudaGetSymbolAddress((void**)&kv,  g_kv);  cudaGetSymbolAddress((void**)&ks,  g_ksum);

    const int GEMM_SMEM = 81920;
    cudaFuncSetAttribute(ta_gemm_bf16, cudaFuncAttributeMaxDynamicSharedMemorySize, GEMM_SMEM);

    // ---- conversions: weights (transpose + hi/lo) and ins (hi/lo)
    ta_wconv<<<cdiv(WT_EMB_SZ,256), 256>>>(embW, OBSD, HID, wth, wtl);
    for (int l = 0; l < NLAY; l++) {
        size_t base = WT_EMB_SZ + (size_t)l * WT_LAYER_SZ;
        ta_wconv<<<cdiv(HID*HID,256), 256>>>(Wq + (size_t)l*HID*HID, HID, HID,
                                             wth + base,          wtl + base);
        ta_wconv<<<cdiv(HID*HID,256), 256>>>(Wk + (size_t)l*HID*HID, HID, HID,
                                             wth + base + 65536,  wtl + base + 65536);
        ta_wconv<<<cdiv(HID*HID,256), 256>>>(Wv + (size_t)l*HID*HID, HID, HID,
                                             wth + base + 131072, wtl + base + 131072);
        ta_wconv<<<cdiv(HID*HID,256), 256>>>(Wo + (size_t)l*HID*HID, HID, HID,
                                             wth + base + 196608, wtl + base + 196608);
        ta_wconv<<<cdiv(HID*FFD,256), 256>>>(W1 + (size_t)l*HID*FFD, HID, FFD,
                                             wth + base + 262144, wtl + base + 262144);
        ta_wconv<<<cdiv(HID*FFD,256), 256>>>(W2 + (size_t)l*FFD*HID, FFD, HID,
                                             wth + base + 524288, wtl + base + 524288);
    }
    {
        int n = BATCH*TLEN*OBSD;
        ta_split<<<cdiv(n,256), 256>>>(ins, insh, insl, n);
    }

    // ---- x row 0 init + embedding GEMM into x rows 1..
    ta_init_hidden<<<BATCH, HID>>>(hidden, resets, xh, xl);
    {
        int M = BATCH * TLEN;  // 65520
        ta_gemm_bf16<<<dim3(HID/128, cdiv(M,128)), 256, GEMM_SMEM>>>(
            insh, insl, wth, wtl, embb, xh, xl, M, OBSD, HID, 0, 1);
    }

    const dim3 g256(HID/128, NTOK/128);   // (2, 512)
    const dim3 gff (FFD/128, NTOK/128);   // (8, 512)

    for (int l = 0; l < NLAY; l++) {
        size_t base = WT_EMB_SZ + (size_t)l * WT_LAYER_SZ;
        const bf16 *qwh = wth + base,          *qwl = wtl + base;
        const bf16 *kwh = wth + base + 65536,  *kwl = wtl + base + 65536;
        const bf16 *vwh = wth + base + 131072, *vwl = wtl + base + 131072;
        const bf16 *owh = wth + base + 196608, *owl = wtl + base + 196608;
        const bf16 *w1h = wth + base + 262144, *w1l = wtl + base + 262144;
        const bf16 *w2h = wth + base + 524288, *w2l = wtl + base + 524288;

        ta_gemm_bf16<<<g256, 256, GEMM_SMEM>>>(xh, xl, qwh, qwl, bq + l*HID,
                                               qph, qpl, NTOK, HID, HID, 1, 0);
        ta_gemm_bf16<<<g256, 256, GEMM_SMEM>>>(xh, xl, kwh, kwl, bk + l*HID,
                                               kph, kpl, NTOK, HID, HID, 1, 0);
        ta_gemm_bf16<<<g256, 256, GEMM_SMEM>>>(xh, xl, vwh, vwl, bv + l*HID,
                                               vh, vl, NTOK, HID, HID, 0, 0);

        ta_zero_kv<<<cdiv(BATCH*NHEAD*DHEAD*DHEAD, 256), 256>>>(kv, ks);
        ta_kv_reduce<<<dim3(8, NHEAD, BATCH), 256>>>(kph, kpl, vh, vl, kv, ks);
        ta_attn_apply<<<dim3(LSEQ/32, BATCH), 256>>>(qph, qpl, kv, ks, ah, al);

        ta_gemm_bf16<<<g256, 256, GEMM_SMEM>>>(ah, al, owh, owl, bo + l*HID,
                                               qph, qpl, NTOK, HID, HID, 0, 0);
        ta_ln2<<<NTOK/8, dim3(32,8)>>>(qph, qpl, ln1s + l*HID, ln1b + l*HID, xh, xl);

        ta_gemm_bf16<<<gff, 256, GEMM_SMEM>>>(xh, xl, w1h, w1l, b1 + l*FFD,
                                              fh, fl, NTOK, HID, FFD, 2, 0);
        ta_gemm_bf16<<<g256, 256, GEMM_SMEM>>>(fh, fl, w2h, w2l, b2 + l*HID,
                                               qph, qpl, NTOK, FFD, HID, 0, 0);
        ta_ln2<<<NTOK/8, dim3(32,8)>>>(qph, qpl, ln2s + l*HID, ln2b + l*HID, xh, xl);
    }

    ta_final<<<1, 512>>>(xh, xl, qpW, qpb, (float*)d_out);
}

// round 4
// speedup vs baseline: 2.0582x; 1.0762x over previous
#include <cuda_runtime.h>
#include <cuda_bf16.h>
#include <cstdint>

// ---------------- problem constants ----------------
#define BATCH 16
#define TLEN  4095
#define LSEQ  4096          // TLEN + 1
#define NTOK  (BATCH*LSEQ)  // 65536
#define OBSD  128
#define HID   256
#define NHEAD 8
#define DHEAD 32
#define FFD   1024
#define NLAY  4
#define QKVW  (3*HID)       // 768
#define KEPS  1e-3f
#define LNEPS 1e-6f

typedef __nv_bfloat16 bf16;

// ---------------- device scratch ----------------
__device__ bf16 g_xh [(size_t)NTOK*HID];    __device__ bf16 g_xl [(size_t)NTOK*HID];
__device__ bf16 g_qkvh[(size_t)NTOK*QKVW];  __device__ bf16 g_qkvl[(size_t)NTOK*QKVW];
__device__ bf16 g_ah [(size_t)NTOK*HID];    __device__ bf16 g_al [(size_t)NTOK*HID];
__device__ bf16 g_zh [(size_t)NTOK*HID];    __device__ bf16 g_zl [(size_t)NTOK*HID];
__device__ bf16 g_fh [(size_t)NTOK*FFD];    __device__ bf16 g_fl [(size_t)NTOK*FFD];
__device__ bf16 g_insh[(size_t)(BATCH*TLEN)*OBSD];
__device__ bf16 g_insl[(size_t)(BATCH*TLEN)*OBSD];
__device__ float g_kv  [BATCH*NHEAD*DHEAD*DHEAD];
__device__ float g_ksum[BATCH*NHEAD*DHEAD];

// transposed bf16 hi/lo weights (WT[N][K] layout)
#define WT_EMB_SZ   (HID*OBSD)
#define WT_LAYER_SZ (4*HID*HID + 2*HID*FFD)
#define WT_TOTAL    (WT_EMB_SZ + NLAY*WT_LAYER_SZ)
__device__ bf16 g_wth[WT_TOTAL];
__device__ bf16 g_wtl[WT_TOTAL];

static inline int cdiv(int a, int b) { return (a + b - 1) / b; }

// ---------------- helpers ----------------
__device__ __forceinline__ uint32_t smem_u32(const void* p) {
    uint32_t a;
    asm("{ .reg .u64 t; cvta.to.shared.u64 t, %1; cvt.u32.u64 %0, t; }" : "=r"(a) : "l"(p));
    return a;
}
__device__ __forceinline__ float hl(const bf16* H, const bf16* L, size_t i) {
    return __bfloat162float(H[i]) + __bfloat162float(L[i]);
}
__device__ __forceinline__ void sphl(float f, bf16* H, bf16* L, size_t i) {
    bf16 h = __float2bfloat16(f);
    H[i] = h;
    L[i] = __float2bfloat16(f - __bfloat162float(h));
}

#define LDSM4(r, addr)                                                     \
    asm volatile("ldmatrix.sync.aligned.m8n8.x4.shared.b16 "               \
                 "{%0,%1,%2,%3}, [%4];"                                    \
                 : "=r"((r)[0]), "=r"((r)[1]), "=r"((r)[2]), "=r"((r)[3])  \
                 : "r"(addr))

#define MMA_BF16(d, a, b0, b1)                                             \
    asm volatile("mma.sync.aligned.m16n8k16.row.col.f32.bf16.bf16.f32 "    \
                 "{%0,%1,%2,%3},{%4,%5,%6,%7},{%8,%9},{%0,%1,%2,%3};"      \
                 : "+f"((d)[0]), "+f"((d)[1]), "+f"((d)[2]), "+f"((d)[3])  \
                 : "r"((a)[0]), "r"((a)[1]), "r"((a)[2]), "r"((a)[3]),     \
                   "r"(b0), "r"(b1))

__device__ __forceinline__ void cpa16(uint32_t dst, const void* src, int sz) {
    asm volatile("cp.async.cg.shared.global [%0], [%1], 16, %2;"
                 :: "r"(dst), "l"(__cvta_generic_to_global(src)), "r"(sz));
}

// ---------------- single-launch weight conversion ----------------
// W[K,N] fp32 -> WT[N,K] bf16 hi/lo, 25 segments: emb + 4 layers x {q,k,v,o,w1,w2}
__global__ void ta_wconv_all(const float* __restrict__ embW,
                             const float* __restrict__ Wq, const float* __restrict__ Wk,
                             const float* __restrict__ Wv, const float* __restrict__ Wo,
                             const float* __restrict__ W1, const float* __restrict__ W2,
                             bf16* __restrict__ hi, bf16* __restrict__ lo) {
    const int seg = blockIdx.y;
    const float* src;
    int K, N;
    size_t dst;
    if (seg == 0) {
        src = embW; K = OBSD; N = HID; dst = 0;
    } else {
        const int l = (seg - 1) / 6, m = (seg - 1) % 6;
        const size_t base = WT_EMB_SZ + (size_t)l * WT_LAYER_SZ;
        switch (m) {
            case 0: src = Wq + (size_t)l*HID*HID; K = HID; N = HID; dst = base;          break;
            case 1: src = Wk + (size_t)l*HID*HID; K = HID; N = HID; dst = base + 65536;  break;
            case 2: src = Wv + (size_t)l*HID*HID; K = HID; N = HID; dst = base + 131072; break;
            case 3: src = Wo + (size_t)l*HID*HID; K = HID; N = HID; dst = base + 196608; break;
            case 4: src = W1 + (size_t)l*HID*FFD; K = HID; N = FFD; dst = base + 262144; break;
            default:src = W2 + (size_t)l*FFD*HID; K = FFD; N = HID; dst = base + 524288; break;
        }
    }
    int i = blockIdx.x * 256 + threadIdx.x;
    if (i >= N * K) return;
    int n = i / K, k = i - n * K;
    float w = src[(size_t)k * N + n];
    bf16 h = __float2bfloat16(w);
    hi[dst + i] = h;
    lo[dst + i] = __float2bfloat16(w - __bfloat162float(h));
}

__global__ void ta_split(const float* __restrict__ src,
                         bf16* __restrict__ H, bf16* __restrict__ L, int n) {
    int i = blockIdx.x * 256 + threadIdx.x;
    if (i < n) sphl(src[i], H, L, i);
}

__global__ void ta_init_hidden(const float* __restrict__ hs,
                               const unsigned char* __restrict__ resets,
                               bf16* __restrict__ XH, bf16* __restrict__ XL) {
    int b = blockIdx.x, c = threadIdx.x;
    float v = resets[b] ? 0.f : hs[b*HID + c];
    sphl(v, XH, XL, (size_t)b*LSEQ*HID + c);
}

// ---------------- bf16 hi/lo 3-pass MMA GEMM ----------------
// C = A @ B^T + bias. Passes: Ah*Bh + Ah*Bl + Al*Bh. CTA tile 128x128, Kc=32,
// 8 warps (2x4), warp tile 64x32, 2-stage cp.async, pad-40 smem rows.
// flags: bit0 = embRemap, bit1 = qkvMode (N=768 fused: cols 0-511 relu+KEPS
// w/ biasQ/biasK, cols 512-767 plain w/ biasV).
__global__ __launch_bounds__(256, 2)
void ta_gemm_bf16(const bf16* __restrict__ Ah, const bf16* __restrict__ Al,
                  const bf16* __restrict__ Bh, const bf16* __restrict__ Bl,
                  const float* __restrict__ bias0, const float* __restrict__ bias1,
                  const float* __restrict__ bias2,
                  bf16* __restrict__ Ch, bf16* __restrict__ Cl,
                  int M, int K, int N, int epi, int flags) {
    extern __shared__ char smem[];
    const uint32_t smu = smem_u32(smem);

    const int tid  = threadIdx.x;
    const int wid  = tid >> 5;
    const int lane = tid & 31;
    const int wr   = wid >> 2;
    const int wc   = wid & 3;
    const int rowBase = blockIdx.y * 128;
    const int colBase = blockIdx.x * 128;

    const int r  = tid >> 2;
    const int ch = tid & 3;

    const uint32_t laneOff = (uint32_t)(((lane & 15) * 40 + ((lane >> 4) << 3)) * 2);
    const uint32_t aWarp = (uint32_t)(wr * 64 * 80);
    const uint32_t bWarp = (uint32_t)(wc * 32 * 80);

    float acc[4][4][4] = {};

    auto load_stage = [&](int st, int kt) {
        const uint32_t sb = smu + st * 40960u;
        const int kOff = kt * 32;
        #pragma unroll
        for (int hf = 0; hf < 2; hf++) {
            const int rr = r + hf * 64;
            const int grow = rowBase + rr;
            const int sz = (grow < M) ? 16 : 0;
            const size_t asrc = (size_t)(sz ? grow : 0) * K + kOff + ch * 8;
            const uint32_t dA = sb + rr * 80 + ch * 16;
            cpa16(dA,          Ah + asrc, sz);
            cpa16(dA + 10240u, Al + asrc, sz);
            const size_t bsrc = (size_t)(colBase + rr) * K + kOff + ch * 8;
            const uint32_t dB = sb + 20480u + rr * 80 + ch * 16;
            cpa16(dB,          Bh + bsrc, 16);
            cpa16(dB + 10240u, Bl + bsrc, 16);
        }
        asm volatile("cp.async.commit_group;");
    };

    auto compute = [&](int st) {
        const uint32_t sb  = smu + st * 40960u;
        const uint32_t aHB = sb + aWarp + laneOff;
        const uint32_t aLB = aHB + 10240u;
        const uint32_t bHB = sb + 20480u + bWarp + laneOff;
        const uint32_t bLB = bHB + 10240u;
        #pragma unroll
        for (int ks = 0; ks < 2; ks++) {
            uint32_t bH[2][4], bL[2][4];
            LDSM4(bH[0], bHB + ks * 32u);
            LDSM4(bH[1], bHB + 1280u + ks * 32u);
            LDSM4(bL[0], bLB + ks * 32u);
            LDSM4(bL[1], bLB + 1280u + ks * 32u);
            uint32_t a[4][4];
            #pragma unroll
            for (int mi = 0; mi < 4; mi++) LDSM4(a[mi], aHB + mi * 1280u + ks * 32u);
            #pragma unroll
            for (int mi = 0; mi < 4; mi++)
                #pragma unroll
                for (int nt = 0; nt < 4; nt++) {
                    MMA_BF16(acc[mi][nt], a[mi], bH[nt >> 1][nt & 1], bH[nt >> 1][(nt & 1) + 2]);
                    MMA_BF16(acc[mi][nt], a[mi], bL[nt >> 1][nt & 1], bL[nt >> 1][(nt & 1) + 2]);
                }
            #pragma unroll
            for (int mi = 0; mi < 4; mi++) LDSM4(a[mi], aLB + mi * 1280u + ks * 32u);
            #pragma unroll
            for (int mi = 0; mi < 4; mi++)
                #pragma unroll
                for (int nt = 0; nt < 4; nt++)
                    MMA_BF16(acc[mi][nt], a[mi], bH[nt >> 1][nt & 1], bH[nt >> 1][(nt & 1) + 2]);
        }
    };

    const int nk = K >> 5;
    load_stage(0, 0);
    for (int kt = 0; kt < nk; kt++) {
        if (kt + 1 < nk) {
            load_stage((kt + 1) & 1, kt + 1);
        } else {
            asm volatile("cp.async.commit_group;");
        }
        asm volatile("cp.async.wait_group 1;");
        __syncthreads();
        compute(kt & 1);
        __syncthreads();
    }

    // ---- epilogue
    const bool embRemap = flags & 1;
    const bool qkvMode  = flags & 2;
    const float* bptr = bias0;
    int ep = epi;
    if (qkvMode) {
        int seg = colBase >> 8;
        bptr = (seg == 0) ? bias0 : (seg == 1) ? bias1 : bias2;
        ep = (seg < 2) ? 1 : 0;
    }
    const int t4 = lane >> 2;
    const int t2 = (lane & 3) << 1;
    #pragma unroll
    for (int mi = 0; mi < 4; mi++) {
        #pragma unroll
        for (int duo = 0; duo < 2; duo++) {
            const int row = rowBase + wr * 64 + mi * 16 + t4 + duo * 8;
            if (row >= M) continue;
            size_t orow = (size_t)row;
            if (embRemap) {
                int b = row / TLEN;
                orow = (size_t)b * LSEQ + 1 + (row - b * TLEN);
            }
            #pragma unroll
            for (int nt = 0; nt < 4; nt++) {
                const int col = colBase + wc * 32 + nt * 8 + t2;
                const int bcol = qkvMode ? (col & 255) : col;
                float c0 = acc[mi][nt][duo * 2 + 0] + bptr[bcol];
                float c1 = acc[mi][nt][duo * 2 + 1] + bptr[bcol + 1];
                if (ep == 1)      { c0 = fmaxf(c0, 0.f) + KEPS; c1 = fmaxf(c1, 0.f) + KEPS; }
                else if (ep == 2) { c0 = fmaxf(c0, 0.f);        c1 = fmaxf(c1, 0.f); }
                bf16 h0 = __float2bfloat16(c0), h1 = __float2bfloat16(c1);
                bf16 l0 = __float2bfloat16(c0 - __bfloat162float(h0));
                bf16 l1 = __float2bfloat16(c1 - __bfloat162float(h1));
                uint32_t hp = (uint32_t)*(uint16_t*)&h0 | ((uint32_t)*(uint16_t*)&h1 << 16);
                uint32_t lp = (uint32_t)*(uint16_t*)&l0 | ((uint32_t)*(uint16_t*)&l1 << 16);
                *(uint32_t*)(Ch + orow * N + col) = hp;
                *(uint32_t*)(Cl + orow * N + col) = lp;
            }
        }
    }
}

// ---------------- zero kv/ksum ----------------
__global__ void ta_zero_kv(float* __restrict__ KV, float* __restrict__ KS) {
    int i = blockIdx.x * 256 + threadIdx.x;
    if (i < BATCH*NHEAD*DHEAD*DHEAD) KV[i] = 0.f;
    if (i < BATCH*NHEAD*DHEAD)       KS[i] = 0.f;
}

// ---------------- kv = sum_l kp (x) v ; ksum = sum_l kp (QKV fused layout) ----
__global__ void ta_kv_reduce(const bf16* __restrict__ QKVh, const bf16* __restrict__ QKVl,
                             float* __restrict__ KV, float* __restrict__ KS) {
    const int s = blockIdx.x, h = blockIdx.y, b = blockIdx.z;
    const int CH = LSEQ / 8;
    const int tid = threadIdx.x;
    const int w = tid >> 5, lane = tid & 31;

    __shared__ float kps[8][32];
    __shared__ float vs [8][32];

    float acc[4] = {0.f, 0.f, 0.f, 0.f};
    float ksa = 0.f;
    const size_t rowBase = (size_t)b * LSEQ + (size_t)s * CH;

    for (int l0 = 0; l0 < CH; l0 += 8) {
        size_t rbase = (rowBase + l0 + w) * QKVW + h * DHEAD + lane;
        kps[w][lane] = hl(QKVh, QKVl, rbase + HID);      // kp at col 256+
        vs [w][lane] = hl(QKVh, QKVl, rbase + 2*HID);    // v  at col 512+
        __syncthreads();
        #pragma unroll
        for (int q = 0; q < 8; q++) {
            float vd = vs[q][lane];
            #pragma unroll
            for (int j = 0; j < 4; j++)
                acc[j] += kps[q][w + 8*j] * vd;
            if (tid < 32) ksa += kps[q][lane];
        }
        __syncthreads();
    }
    const int bh = b * NHEAD + h;
    #pragma unroll
    for (int j = 0; j < 4; j++)
        atomicAdd(&KV[bh*1024 + (w + 8*j)*32 + lane], acc[j]);
    if (tid < 32) atomicAdd(&KS[bh*32 + lane], ksa);
}

// ---------------- a = (qp @ kv) / (qp . ksum) ----------------
__global__ void ta_attn_apply(const bf16* __restrict__ QKVh, const bf16* __restrict__ QKVl,
                              const float* __restrict__ KV, const float* __restrict__ KS,
                              bf16* __restrict__ AH, bf16* __restrict__ AL) {
    __shared__ float kvs[8 * 1028];
    __shared__ float kss[8 * 32];

    const int b = blockIdx.y;
    const int tokBase = blockIdx.x * 32;
    const int tid = threadIdx.x;

    for (int i = tid; i < 8 * 1024; i += 256) {
        int h = i >> 10, rr = i & 1023;
        kvs[h * 1028 + rr] = KV[(b*NHEAD + h)*1024 + rr];
    }
    kss[tid] = KS[b * (NHEAD*DHEAD) + tid];
    __syncthreads();

    const int w = tid >> 5, lane = tid & 31;
    const int h = lane >> 2, tk = lane & 3;
    const int tok = tokBase + w * 4 + tk;
    const size_t qrow = ((size_t)b * LSEQ + tok) * QKVW + h * DHEAD;
    const size_t arow = ((size_t)b * LSEQ + tok) * HID  + h * DHEAD;

    float qv[32];
    float den = 0.f;
    #pragma unroll
    for (int m = 0; m < 32; m++) {
        qv[m] = hl(QKVh, QKVl, qrow + m);
        den += qv[m] * kss[h*32 + m];
    }
    const float inv = 1.f / den;
    const float* kvh = &kvs[h * 1028];
    #pragma unroll
    for (int d = 0; d < 32; d++) {
        float sacc = 0.f;
        #pragma unroll
        for (int m = 0; m < 32; m++)
            sacc += qv[m] * kvh[m*32 + d];
        sphl(sacc * inv, AH, AL, arow + d);
    }
}

// ---------------- X = LN(2*Z)*scale + bias ----------------
__global__ void ta_ln2(const bf16* __restrict__ ZH, const bf16* __restrict__ ZL,
                       const float* __restrict__ sc, const float* __restrict__ bi,
                       bf16* __restrict__ XH, bf16* __restrict__ XL) {
    const int row  = blockIdx.x * 8 + threadIdx.y;
    const int lane = threadIdx.x;
    const size_t base = (size_t)row * HID;

    float v[8];
    float sum = 0.f;
    #pragma unroll
    for (int j = 0; j < 8; j++) { v[j] = 2.f * hl(ZH, ZL, base + lane + j*32); sum += v[j]; }
    #pragma unroll
    for (int o = 16; o; o >>= 1) sum += __shfl_xor_sync(0xffffffffu, sum, o);
    const float mean = sum * (1.f / HID);

    float vs = 0.f;
    #pragma unroll
    for (int j = 0; j < 8; j++) { float d = v[j] - mean; vs += d * d; }
    #pragma unroll
    for (int o = 16; o; o >>= 1) vs += __shfl_xor_sync(0xffffffffu, vs, o);
    const float rr = rsqrtf(vs * (1.f / HID) + LNEPS);

    #pragma unroll
    for (int j = 0; j < 8; j++) {
        int c = lane + j*32;
        sphl((v[j] - mean) * rr * sc[c] + bi[c], XH, XL, base + c);
    }
}

// ---------------- final readout ----------------
__global__ void ta_final(const bf16* __restrict__ XH, const bf16* __restrict__ XL,
                         const float* __restrict__ qpW, const float* __restrict__ qpb,
                         float* __restrict__ out) {
    const int tid = threadIdx.x;   // 512
    for (int i = tid; i < BATCH*HID; i += 512) {
        int b = i >> 8, c = i & 255;
        out[i] = hl(XH, XL, (size_t)b * LSEQ * HID + c);
    }
    const int b = tid >> 5, j = tid & 31;
    const size_t xr = (size_t)b * LSEQ * HID;
    float s = qpb[j];
    #pragma unroll 8
    for (int c = 0; c < HID; c++) s += hl(XH, XL, xr + c) * qpW[c*32 + j];
    out[BATCH*HID + tid] = s;
}

// ---------------- launcher ----------------
extern "C" void kernel_launch(void* const* d_in, const int* in_sizes, int n_in,
                              void* d_out, int out_size) {
    const float* hidden = (const float*)d_in[0];
    const float* ins    = (const float*)d_in[1];
    const unsigned char* resets = (const unsigned char*)d_in[2];
    const float* embW = (const float*)d_in[3];
    const float* embb = (const float*)d_in[4];
    const float* Wq = (const float*)d_in[5];
    const float* bq = (const float*)d_in[6];
    const float* Wk = (const float*)d_in[7];
    const float* bk = (const float*)d_in[8];
    const float* Wv = (const float*)d_in[9];
    const float* bv = (const float*)d_in[10];
    const float* Wo = (const float*)d_in[11];
    const float* bo = (const float*)d_in[12];
    const float* ln1s = (const float*)d_in[13];
    const float* ln1b = (const float*)d_in[14];
    const float* W1 = (const float*)d_in[15];
    const float* b1 = (const float*)d_in[16];
    const float* W2 = (const float*)d_in[17];
    const float* b2 = (const float*)d_in[18];
    const float* ln2s = (const float*)d_in[19];
    const float* ln2b = (const float*)d_in[20];
    const float* qpW = (const float*)d_in[21];
    const float* qpb = (const float*)d_in[22];

    bf16 *xh,*xl,*qkvh,*qkvl,*ah,*al,*zh,*zl,*fh,*fl,*insh,*insl,*wth,*wtl;
    float *kv, *ks;
    cudaGetSymbolAddress((void**)&xh,   g_xh);   cudaGetSymbolAddress((void**)&xl,   g_xl);
    cudaGetSymbolAddress((void**)&qkvh, g_qkvh); cudaGetSymbolAddress((void**)&qkvl, g_qkvl);
    cudaGetSymbolAddress((void**)&ah,   g_ah);   cudaGetSymbolAddress((void**)&al,   g_al);
    cudaGetSymbolAddress((void**)&zh,   g_zh);   cudaGetSymbolAddress((void**)&zl,   g_zl);
    cudaGetSymbolAddress((void**)&fh,   g_fh);   cudaGetSymbolAddress((void**)&fl,   g_fl);
    cudaGetSymbolAddress((void**)&insh, g_insh); cudaGetSymbolAddress((void**)&insl, g_insl);
    cudaGetSymbolAddress((void**)&wth,  g_wth);  cudaGetSymbolAddress((void**)&wtl,  g_wtl);
    cudaGetSymbolAddress((void**)&kv,   g_kv);   cudaGetSymbolAddress((void**)&ks,   g_ksum);

    const int GEMM_SMEM = 81920;
    cudaFuncSetAttribute(ta_gemm_bf16, cudaFuncAttributeMaxDynamicSharedMemorySize, GEMM_SMEM);

    // L0: all weight conversion in one launch
    ta_wconv_all<<<dim3(1024, 25), 256>>>(embW, Wq, Wk, Wv, Wo, W1, W2, wth, wtl);
    // L1: split ins
    {
        int n = BATCH*TLEN*OBSD;
        ta_split<<<cdiv(n,256), 256>>>(ins, insh, insl, n);
    }
    // L2: hidden row init
    ta_init_hidden<<<BATCH, HID>>>(hidden, resets, xh, xl);
    // L3: embedding GEMM into x rows 1..
    {
        int M = BATCH * TLEN;
        ta_gemm_bf16<<<dim3(HID/128, cdiv(M,128)), 256, GEMM_SMEM>>>(
            insh, insl, wth, wtl, embb, embb, embb, xh, xl, M, OBSD, HID, 0, 1);
    }

    const dim3 gqkv(QKVW/128, NTOK/128);  // (6, 512)
    const dim3 g256(HID/128,  NTOK/128);  // (2, 512)
    const dim3 gff (FFD/128,  NTOK/128);  // (8, 512)

    for (int l = 0; l < NLAY; l++) {
        size_t base = WT_EMB_SZ + (size_t)l * WT_LAYER_SZ;
        const bf16 *qkvwh = wth + base,          *qkvwl = wtl + base;           // q,k,v contiguous
        const bf16 *owh   = wth + base + 196608, *owl   = wtl + base + 196608;
        const bf16 *w1h   = wth + base + 262144, *w1l   = wtl + base + 262144;
        const bf16 *w2h   = wth + base + 524288, *w2l   = wtl + base + 524288;

        // L4 (layer 0): zero kv, then L5: fused QKV GEMM (ncu -s 5 profiles this)
        ta_zero_kv<<<cdiv(BATCH*NHEAD*DHEAD*DHEAD, 256), 256>>>(kv, ks);
        ta_gemm_bf16<<<gqkv, 256, GEMM_SMEM>>>(xh, xl, qkvwh, qkvwl,
                                               bq + l*HID, bk + l*HID, bv + l*HID,
                                               qkvh, qkvl, NTOK, HID, QKVW, 0, 2);

        ta_kv_reduce<<<dim3(8, NHEAD, BATCH), 256>>>(qkvh, qkvl, kv, ks);
        ta_attn_apply<<<dim3(LSEQ/32, BATCH), 256>>>(qkvh, qkvl, kv, ks, ah, al);

        ta_gemm_bf16<<<g256, 256, GEMM_SMEM>>>(ah, al, owh, owl,
                                               bo + l*HID, bo + l*HID, bo + l*HID,
                                               zh, zl, NTOK, HID, HID, 0, 0);
        ta_ln2<<<NTOK/8, dim3(32,8)>>>(zh, zl, ln1s + l*HID, ln1b + l*HID, xh, xl);

        ta_gemm_bf16<<<gff, 256, GEMM_SMEM>>>(xh, xl, w1h, w1l,
                                              b1 + l*FFD, b1 + l*FFD, b1 + l*FFD,
                                              fh, fl, NTOK, HID, FFD, 2, 0);
        ta_gemm_bf16<<<g256, 256, GEMM_SMEM>>>(fh, fl, w2h, w2l,
                                               b2 + l*HID, b2 + l*HID, b2 + l*HID,
                                               zh, zl, NTOK, FFD, HID, 0, 0);
        ta_ln2<<<NTOK/8, dim3(32,8)>>>(zh, zl, ln2s + l*HID, ln2b + l*HID, xh, xl);
    }

    ta_final<<<1, 512>>>(xh, xl, qpW, qpb, (float*)d_out);
}

// round 5
// speedup vs baseline: 2.2669x; 1.1014x over previous
#include <cuda_runtime.h>
#include <cuda_bf16.h>
#include <cstdint>

// ---------------- problem constants ----------------
#define BATCH 16
#define TLEN  4095
#define LSEQ  4096          // TLEN + 1
#define NTOK  (BATCH*LSEQ)  // 65536
#define OBSD  128
#define HID   256
#define NHEAD 8
#define DHEAD 32
#define FFD   1024
#define NLAY  4
#define QKVW  (3*HID)       // 768
#define KEPS  1e-3f
#define LNEPS 1e-6f

typedef __nv_bfloat16 bf16;

// ---------------- device scratch ----------------
__device__ bf16 g_xh [(size_t)NTOK*HID];    __device__ bf16 g_xl [(size_t)NTOK*HID];
__device__ bf16 g_qkvh[(size_t)NTOK*QKVW];  __device__ bf16 g_qkvl[(size_t)NTOK*QKVW];
__device__ bf16 g_ah [(size_t)NTOK*HID];    __device__ bf16 g_al [(size_t)NTOK*HID];
__device__ bf16 g_zh [(size_t)NTOK*HID];    __device__ bf16 g_zl [(size_t)NTOK*HID];
__device__ bf16 g_fh [(size_t)NTOK*FFD];    __device__ bf16 g_fl [(size_t)NTOK*FFD];
__device__ bf16 g_insh[(size_t)(BATCH*TLEN)*OBSD];
__device__ bf16 g_insl[(size_t)(BATCH*TLEN)*OBSD];
__device__ float g_kv  [BATCH*NHEAD*DHEAD*DHEAD];
__device__ float g_ksum[BATCH*NHEAD*DHEAD];

// transposed bf16 hi/lo weights (WT[N][K] layout)
#define WT_EMB_SZ   (HID*OBSD)
#define WT_LAYER_SZ (4*HID*HID + 2*HID*FFD)
#define WT_TOTAL    (WT_EMB_SZ + NLAY*WT_LAYER_SZ)
__device__ bf16 g_wth[WT_TOTAL];
__device__ bf16 g_wtl[WT_TOTAL];

static inline int cdiv(int a, int b) { return (a + b - 1) / b; }

// ---------------- helpers ----------------
__device__ __forceinline__ uint32_t smem_u32(const void* p) {
    uint32_t a;
    asm("{ .reg .u64 t; cvta.to.shared.u64 t, %1; cvt.u32.u64 %0, t; }" : "=r"(a) : "l"(p));
    return a;
}
__device__ __forceinline__ float hl(const bf16* H, const bf16* L, size_t i) {
    return __bfloat162float(H[i]) + __bfloat162float(L[i]);
}
__device__ __forceinline__ void sphl(float f, bf16* H, bf16* L, size_t i) {
    bf16 h = __float2bfloat16(f);
    H[i] = h;
    L[i] = __float2bfloat16(f - __bfloat162float(h));
}

#define LDSM4(r, addr)                                                     \
    asm volatile("ldmatrix.sync.aligned.m8n8.x4.shared.b16 "               \
                 "{%0,%1,%2,%3}, [%4];"                                    \
                 : "=r"((r)[0]), "=r"((r)[1]), "=r"((r)[2]), "=r"((r)[3])  \
                 : "r"(addr))

#define MMA_BF16(d, a, b0, b1)                                             \
    asm volatile("mma.sync.aligned.m16n8k16.row.col.f32.bf16.bf16.f32 "    \
                 "{%0,%1,%2,%3},{%4,%5,%6,%7},{%8,%9},{%0,%1,%2,%3};"      \
                 : "+f"((d)[0]), "+f"((d)[1]), "+f"((d)[2]), "+f"((d)[3])  \
                 : "r"((a)[0]), "r"((a)[1]), "r"((a)[2]), "r"((a)[3]),     \
                   "r"(b0), "r"(b1))

__device__ __forceinline__ void cpa16(uint32_t dst, const void* src, int sz) {
    asm volatile("cp.async.cg.shared.global [%0], [%1], 16, %2;"
                 :: "r"(dst), "l"(__cvta_generic_to_global(src)), "r"(sz));
}

// ---------------- single-launch weight conversion ----------------
__global__ void ta_wconv_all(const float* __restrict__ embW,
                             const float* __restrict__ Wq, const float* __restrict__ Wk,
                             const float* __restrict__ Wv, const float* __restrict__ Wo,
                             const float* __restrict__ W1, const float* __restrict__ W2,
                             bf16* __restrict__ hi, bf16* __restrict__ lo) {
    const int seg = blockIdx.y;
    const float* src;
    int K, N;
    size_t dst;
    if (seg == 0) {
        src = embW; K = OBSD; N = HID; dst = 0;
    } else {
        const int l = (seg - 1) / 6, m = (seg - 1) % 6;
        const size_t base = WT_EMB_SZ + (size_t)l * WT_LAYER_SZ;
        switch (m) {
            case 0: src = Wq + (size_t)l*HID*HID; K = HID; N = HID; dst = base;          break;
            case 1: src = Wk + (size_t)l*HID*HID; K = HID; N = HID; dst = base + 65536;  break;
            case 2: src = Wv + (size_t)l*HID*HID; K = HID; N = HID; dst = base + 131072; break;
            case 3: src = Wo + (size_t)l*HID*HID; K = HID; N = HID; dst = base + 196608; break;
            case 4: src = W1 + (size_t)l*HID*FFD; K = HID; N = FFD; dst = base + 262144; break;
            default:src = W2 + (size_t)l*FFD*HID; K = FFD; N = HID; dst = base + 524288; break;
        }
    }
    int i = blockIdx.x * 256 + threadIdx.x;
    if (i >= N * K) return;
    int n = i / K, k = i - n * K;
    float w = src[(size_t)k * N + n];
    bf16 h = __float2bfloat16(w);
    hi[dst + i] = h;
    lo[dst + i] = __float2bfloat16(w - __bfloat162float(h));
}

__global__ void ta_split(const float* __restrict__ src,
                         bf16* __restrict__ H, bf16* __restrict__ L, int n) {
    int i = blockIdx.x * 256 + threadIdx.x;
    if (i < n) sphl(src[i], H, L, i);
}

__global__ void ta_init_hidden(const float* __restrict__ hs,
                               const unsigned char* __restrict__ resets,
                               bf16* __restrict__ XH, bf16* __restrict__ XL) {
    int b = blockIdx.x, c = threadIdx.x;
    float v = resets[b] ? 0.f : hs[b*HID + c];
    sphl(v, XH, XL, (size_t)b*LSEQ*HID + c);
}

// ---------------- bf16 hi/lo 3-pass MMA GEMM (3-stage, swizzled) ----------------
// C = A @ B^T + bias. Passes: Ah*Bh + Ah*Bl + Al*Bh. CTA tile 128x128, Kc=32,
// 8 warps (2x4), warp tile 64x32.
// smem tile: 128 rows x 32 bf16 (64B), XOR swizzle: phys_chunk = chunk ^ ((row>>1)&3).
// stage = Ah(8K) Al(8K) Bh(8K) Bl(8K) = 32KB; 3 stages = 96KB; prefetch distance 2,
// ONE __syncthreads per k-iteration.
// flags: bit0 = embRemap, bit1 = qkvMode.
__global__ __launch_bounds__(256, 2)
void ta_gemm_bf16(const bf16* __restrict__ Ah, const bf16* __restrict__ Al,
                  const bf16* __restrict__ Bh, const bf16* __restrict__ Bl,
                  const float* __restrict__ bias0, const float* __restrict__ bias1,
                  const float* __restrict__ bias2,
                  bf16* __restrict__ Ch, bf16* __restrict__ Cl,
                  int M, int K, int N, int epi, int flags) {
    extern __shared__ char smem[];
    const uint32_t smu = smem_u32(smem);

    const int tid  = threadIdx.x;
    const int wid  = tid >> 5;
    const int lane = tid & 31;
    const int wr   = wid >> 2;
    const int wc   = wid & 3;
    const int rowBase = blockIdx.y * 128;
    const int colBase = blockIdx.x * 128;

    // cp.async mapping: thread -> (row r, 16B chunk ch); handles rows r and r+64
    const int r  = tid >> 2;
    const int ch = tid & 3;
    const uint32_t stOff = (uint32_t)(r * 64 + ((ch ^ ((r >> 1) & 3)) << 4));
    const uint32_t stOff2 = (uint32_t)((r + 64) * 64 + ((ch ^ (((r + 64) >> 1) & 3)) << 4));

    // ldmatrix per-lane offsets (within a tile)
    const int r15 = lane & 15;
    const int hi_ = lane >> 4;
    const int sw  = (r15 >> 1) & 3;
    const uint32_t rowB  = (uint32_t)(r15 * 64);
    const uint32_t co0   = rowB + (uint32_t)(((hi_    ) ^ sw) << 4);  // ks=0 chunks {0,1}
    const uint32_t co1   = rowB + (uint32_t)(((2 + hi_) ^ sw) << 4);  // ks=1 chunks {2,3}
    const uint32_t aWarp = (uint32_t)(wr * 4096);   // 64 rows * 64B
    const uint32_t bWarp = (uint32_t)(wc * 2048);   // 32 rows * 64B

    float acc[4][4][4] = {};

    auto load_stage = [&](int st, int kt) {
        const uint32_t sb = smu + (uint32_t)st * 32768u;
        const int kOff = kt * 32 + ch * 8;
        // ---- rows r and r+64 for A and B, hi and lo
        {
            const int grow = rowBase + r;
            const int sz = (grow < M) ? 16 : 0;
            const size_t asrc = (size_t)(sz ? grow : 0) * K + kOff;
            cpa16(sb + stOff,          Ah + asrc, sz);
            cpa16(sb + 8192u + stOff,  Al + asrc, sz);
            const size_t bsrc = (size_t)(colBase + r) * K + kOff;
            cpa16(sb + 16384u + stOff, Bh + bsrc, 16);
            cpa16(sb + 24576u + stOff, Bl + bsrc, 16);
        }
        {
            const int grow = rowBase + r + 64;
            const int sz = (grow < M) ? 16 : 0;
            const size_t asrc = (size_t)(sz ? grow : 0) * K + kOff;
            cpa16(sb + stOff2,          Ah + asrc, sz);
            cpa16(sb + 8192u + stOff2,  Al + asrc, sz);
            const size_t bsrc = (size_t)(colBase + r + 64) * K + kOff;
            cpa16(sb + 16384u + stOff2, Bh + bsrc, 16);
            cpa16(sb + 24576u + stOff2, Bl + bsrc, 16);
        }
        asm volatile("cp.async.commit_group;");
    };

    auto compute = [&](int st) {
        const uint32_t sb  = smu + (uint32_t)st * 32768u;
        const uint32_t aHB = sb + aWarp;
        const uint32_t aLB = aHB + 8192u;
        const uint32_t bHB = sb + 16384u + bWarp;
        const uint32_t bLB = bHB + 8192u;
        #pragma unroll
        for (int ks = 0; ks < 2; ks++) {
            const uint32_t co = ks ? co1 : co0;
            uint32_t bH[2][4], bL[2][4];
            LDSM4(bH[0], bHB + co);
            LDSM4(bH[1], bHB + 1024u + co);
            LDSM4(bL[0], bLB + co);
            LDSM4(bL[1], bLB + 1024u + co);
            uint32_t a[4][4];
            #pragma unroll
            for (int mi = 0; mi < 4; mi++) LDSM4(a[mi], aHB + mi * 1024u + co);
            #pragma unroll
            for (int mi = 0; mi < 4; mi++)
                #pragma unroll
                for (int nt = 0; nt < 4; nt++) {
                    MMA_BF16(acc[mi][nt], a[mi], bH[nt >> 1][nt & 1], bH[nt >> 1][(nt & 1) + 2]);
                    MMA_BF16(acc[mi][nt], a[mi], bL[nt >> 1][nt & 1], bL[nt >> 1][(nt & 1) + 2]);
                }
            #pragma unroll
            for (int mi = 0; mi < 4; mi++) LDSM4(a[mi], aLB + mi * 1024u + co);
            #pragma unroll
            for (int mi = 0; mi < 4; mi++)
                #pragma unroll
                for (int nt = 0; nt < 4; nt++)
                    MMA_BF16(acc[mi][nt], a[mi], bH[nt >> 1][nt & 1], bH[nt >> 1][(nt & 1) + 2]);
        }
    };

    const int nk = K >> 5;
    load_stage(0, 0);
    load_stage(1, 1);
    int cs = 0, ls = 2;     // compute stage, next load stage
    for (int kt = 0; kt < nk; kt++) {
        if (kt == nk - 1) asm volatile("cp.async.wait_group 0;");
        else              asm volatile("cp.async.wait_group 1;");
        __syncthreads();
        if (kt + 2 < nk) {
            load_stage(ls, kt + 2);
            ls = (ls == 2) ? 0 : ls + 1;
        }
        compute(cs);
        cs = (cs == 2) ? 0 : cs + 1;
    }

    // ---- epilogue
    const bool embRemap = flags & 1;
    const bool qkvMode  = flags & 2;
    const float* bptr = bias0;
    int ep = epi;
    if (qkvMode) {
        int seg = colBase >> 8;
        bptr = (seg == 0) ? bias0 : (seg == 1) ? bias1 : bias2;
        ep = (seg < 2) ? 1 : 0;
    }
    const int t4 = lane >> 2;
    const int t2 = (lane & 3) << 1;
    #pragma unroll
    for (int mi = 0; mi < 4; mi++) {
        #pragma unroll
        for (int duo = 0; duo < 2; duo++) {
            const int row = rowBase + wr * 64 + mi * 16 + t4 + duo * 8;
            if (row >= M) continue;
            size_t orow = (size_t)row;
            if (embRemap) {
                int b = row / TLEN;
                orow = (size_t)b * LSEQ + 1 + (row - b * TLEN);
            }
            #pragma unroll
            for (int nt = 0; nt < 4; nt++) {
                const int col = colBase + wc * 32 + nt * 8 + t2;
                const int bcol = qkvMode ? (col & 255) : col;
                float c0 = acc[mi][nt][duo * 2 + 0] + bptr[bcol];
                float c1 = acc[mi][nt][duo * 2 + 1] + bptr[bcol + 1];
                if (ep == 1)      { c0 = fmaxf(c0, 0.f) + KEPS; c1 = fmaxf(c1, 0.f) + KEPS; }
                else if (ep == 2) { c0 = fmaxf(c0, 0.f);        c1 = fmaxf(c1, 0.f); }
                bf16 h0 = __float2bfloat16(c0), h1 = __float2bfloat16(c1);
                bf16 l0 = __float2bfloat16(c0 - __bfloat162float(h0));
                bf16 l1 = __float2bfloat16(c1 - __bfloat162float(h1));
                uint32_t hp = (uint32_t)*(uint16_t*)&h0 | ((uint32_t)*(uint16_t*)&h1 << 16);
                uint32_t lp = (uint32_t)*(uint16_t*)&l0 | ((uint32_t)*(uint16_t*)&l1 << 16);
                *(uint32_t*)(Ch + orow * N + col) = hp;
                *(uint32_t*)(Cl + orow * N + col) = lp;
            }
        }
    }
}

// ---------------- zero kv/ksum ----------------
__global__ void ta_zero_kv(float* __restrict__ KV, float* __restrict__ KS) {
    int i = blockIdx.x * 256 + threadIdx.x;
    if (i < BATCH*NHEAD*DHEAD*DHEAD) KV[i] = 0.f;
    if (i < BATCH*NHEAD*DHEAD)       KS[i] = 0.f;
}

// ---------------- kv = sum_l kp (x) v ; ksum = sum_l kp ----------------
__global__ void ta_kv_reduce(const bf16* __restrict__ QKVh, const bf16* __restrict__ QKVl,
                             float* __restrict__ KV, float* __restrict__ KS) {
    const int s = blockIdx.x, h = blockIdx.y, b = blockIdx.z;
    const int CH = LSEQ / 8;
    const int tid = threadIdx.x;
    const int w = tid >> 5, lane = tid & 31;

    __shared__ float kps[8][32];
    __shared__ float vs [8][32];

    float acc[4] = {0.f, 0.f, 0.f, 0.f};
    float ksa = 0.f;
    const size_t rowBase = (size_t)b * LSEQ + (size_t)s * CH;

    for (int l0 = 0; l0 < CH; l0 += 8) {
        size_t rbase = (rowBase + l0 + w) * QKVW + h * DHEAD + lane;
        kps[w][lane] = hl(QKVh, QKVl, rbase + HID);
        vs [w][lane] = hl(QKVh, QKVl, rbase + 2*HID);
        __syncthreads();
        #pragma unroll
        for (int q = 0; q < 8; q++) {
            float vd = vs[q][lane];
            #pragma unroll
            for (int j = 0; j < 4; j++)
                acc[j] += kps[q][w + 8*j] * vd;
            if (tid < 32) ksa += kps[q][lane];
        }
        __syncthreads();
    }
    const int bh = b * NHEAD + h;
    #pragma unroll
    for (int j = 0; j < 4; j++)
        atomicAdd(&KV[bh*1024 + (w + 8*j)*32 + lane], acc[j]);
    if (tid < 32) atomicAdd(&KS[bh*32 + lane], ksa);
}

// ---------------- a = (qp @ kv) / (qp . ksum) ----------------
__global__ void ta_attn_apply(const bf16* __restrict__ QKVh, const bf16* __restrict__ QKVl,
                              const float* __restrict__ KV, const float* __restrict__ KS,
                              bf16* __restrict__ AH, bf16* __restrict__ AL) {
    __shared__ float kvs[8 * 1028];
    __shared__ float kss[8 * 32];

    const int b = blockIdx.y;
    const int tokBase = blockIdx.x * 32;
    const int tid = threadIdx.x;

    for (int i = tid; i < 8 * 1024; i += 256) {
        int h = i >> 10, rr = i & 1023;
        kvs[h * 1028 + rr] = KV[(b*NHEAD + h)*1024 + rr];
    }
    kss[tid] = KS[b * (NHEAD*DHEAD) + tid];
    __syncthreads();

    const int w = tid >> 5, lane = tid & 31;
    const int h = lane >> 2, tk = lane & 3;
    const int tok = tokBase + w * 4 + tk;
    const size_t qrow = ((size_t)b * LSEQ + tok) * QKVW + h * DHEAD;
    const size_t arow = ((size_t)b * LSEQ + tok) * HID  + h * DHEAD;

    float qv[32];
    float den = 0.f;
    #pragma unroll
    for (int m = 0; m < 32; m++) {
        qv[m] = hl(QKVh, QKVl, qrow + m);
        den += qv[m] * kss[h*32 + m];
    }
    const float inv = 1.f / den;
    const float* kvh = &kvs[h * 1028];
    #pragma unroll
    for (int d = 0; d < 32; d++) {
        float sacc = 0.f;
        #pragma unroll
        for (int m = 0; m < 32; m++)
            sacc += qv[m] * kvh[m*32 + d];
        sphl(sacc * inv, AH, AL, arow + d);
    }
}

// ---------------- X = LN(2*Z)*scale + bias ----------------
__global__ void ta_ln2(const bf16* __restrict__ ZH, const bf16* __restrict__ ZL,
                       const float* __restrict__ sc, const float* __restrict__ bi,
                       bf16* __restrict__ XH, bf16* __restrict__ XL) {
    const int row  = blockIdx.x * 8 + threadIdx.y;
    const int lane = threadIdx.x;
    const size_t base = (size_t)row * HID;

    float v[8];
    float sum = 0.f;
    #pragma unroll
    for (int j = 0; j < 8; j++) { v[j] = 2.f * hl(ZH, ZL, base + lane + j*32); sum += v[j]; }
    #pragma unroll
    for (int o = 16; o; o >>= 1) sum += __shfl_xor_sync(0xffffffffu, sum, o);
    const float mean = sum * (1.f / HID);

    float vs = 0.f;
    #pragma unroll
    for (int j = 0; j < 8; j++) { float d = v[j] - mean; vs += d * d; }
    #pragma unroll
    for (int o = 16; o; o >>= 1) vs += __shfl_xor_sync(0xffffffffu, vs, o);
    const float rr = rsqrtf(vs * (1.f / HID) + LNEPS);

    #pragma unroll
    for (int j = 0; j < 8; j++) {
        int c = lane + j*32;
        sphl((v[j] - mean) * rr * sc[c] + bi[c], XH, XL, base + c);
    }
}

// ---------------- final readout ----------------
__global__ void ta_final(const bf16* __restrict__ XH, const bf16* __restrict__ XL,
                         const float* __restrict__ qpW, const float* __restrict__ qpb,
                         float* __restrict__ out) {
    const int tid = threadIdx.x;   // 512
    for (int i = tid; i < BATCH*HID; i += 512) {
        int b = i >> 8, c = i & 255;
        out[i] = hl(XH, XL, (size_t)b * LSEQ * HID + c);
    }
    const int b = tid >> 5, j = tid & 31;
    const size_t xr = (size_t)b * LSEQ * HID;
    float s = qpb[j];
    #pragma unroll 8
    for (int c = 0; c < HID; c++) s += hl(XH, XL, xr + c) * qpW[c*32 + j];
    out[BATCH*HID + tid] = s;
}

// ---------------- launcher ----------------
extern "C" void kernel_launch(void* const* d_in, const int* in_sizes, int n_in,
                              void* d_out, int out_size) {
    const float* hidden = (const float*)d_in[0];
    const float* ins    = (const float*)d_in[1];
    const unsigned char* resets = (const unsigned char*)d_in[2];
    const float* embW = (const float*)d_in[3];
    const float* embb = (const float*)d_in[4];
    const float* Wq = (const float*)d_in[5];
    const float* bq = (const float*)d_in[6];
    const float* Wk = (const float*)d_in[7];
    const float* bk = (const float*)d_in[8];
    const float* Wv = (const float*)d_in[9];
    const float* bv = (const float*)d_in[10];
    const float* Wo = (const float*)d_in[11];
    const float* bo = (const float*)d_in[12];
    const float* ln1s = (const float*)d_in[13];
    const float* ln1b = (const float*)d_in[14];
    const float* W1 = (const float*)d_in[15];
    const float* b1 = (const float*)d_in[16];
    const float* W2 = (const float*)d_in[17];
    const float* b2 = (const float*)d_in[18];
    const float* ln2s = (const float*)d_in[19];
    const float* ln2b = (const float*)d_in[20];
    const float* qpW = (const float*)d_in[21];
    const float* qpb = (const float*)d_in[22];

    bf16 *xh,*xl,*qkvh,*qkvl,*ah,*al,*zh,*zl,*fh,*fl,*insh,*insl,*wth,*wtl;
    float *kv, *ks;
    cudaGetSymbolAddress((void**)&xh,   g_xh);   cudaGetSymbolAddress((void**)&xl,   g_xl);
    cudaGetSymbolAddress((void**)&qkvh, g_qkvh); cudaGetSymbolAddress((void**)&qkvl, g_qkvl);
    cudaGetSymbolAddress((void**)&ah,   g_ah);   cudaGetSymbolAddress((void**)&al,   g_al);
    cudaGetSymbolAddress((void**)&zh,   g_zh);   cudaGetSymbolAddress((void**)&zl,   g_zl);
    cudaGetSymbolAddress((void**)&fh,   g_fh);   cudaGetSymbolAddress((void**)&fl,   g_fl);
    cudaGetSymbolAddress((void**)&insh, g_insh); cudaGetSymbolAddress((void**)&insl, g_insl);
    cudaGetSymbolAddress((void**)&wth,  g_wth);  cudaGetSymbolAddress((void**)&wtl,  g_wtl);
    cudaGetSymbolAddress((void**)&kv,   g_kv);   cudaGetSymbolAddress((void**)&ks,   g_ksum);

    const int GEMM_SMEM = 98304;   // 3 stages x 32KB
    cudaFuncSetAttribute(ta_gemm_bf16, cudaFuncAttributeMaxDynamicSharedMemorySize, GEMM_SMEM);

    ta_wconv_all<<<dim3(1024, 25), 256>>>(embW, Wq, Wk, Wv, Wo, W1, W2, wth, wtl);
    {
        int n = BATCH*TLEN*OBSD;
        ta_split<<<cdiv(n,256), 256>>>(ins, insh, insl, n);
    }
    ta_init_hidden<<<BATCH, HID>>>(hidden, resets, xh, xl);
    {
        int M = BATCH * TLEN;
        ta_gemm_bf16<<<dim3(HID/128, cdiv(M,128)), 256, GEMM_SMEM>>>(
            insh, insl, wth, wtl, embb, embb, embb, xh, xl, M, OBSD, HID, 0, 1);
    }

    const dim3 gqkv(QKVW/128, NTOK/128);  // (6, 512)
    const dim3 g256(HID/128,  NTOK/128);  // (2, 512)
    const dim3 gff (FFD/128,  NTOK/128);  // (8, 512)

    for (int l = 0; l < NLAY; l++) {
        size_t base = WT_EMB_SZ + (size_t)l * WT_LAYER_SZ;
        const bf16 *qkvwh = wth + base,          *qkvwl = wtl + base;
        const bf16 *owh   = wth + base + 196608, *owl   = wtl + base + 196608;
        const bf16 *w1h   = wth + base + 262144, *w1l   = wtl + base + 262144;
        const bf16 *w2h   = wth + base + 524288, *w2l   = wtl + base + 524288;

        ta_zero_kv<<<cdiv(BATCH*NHEAD*DHEAD*DHEAD, 256), 256>>>(kv, ks);
        ta_gemm_bf16<<<gqkv, 256, GEMM_SMEM>>>(xh, xl, qkvwh, qkvwl,
                                               bq + l*HID, bk + l*HID, bv + l*HID,
                                               qkvh, qkvl, NTOK, HID, QKVW, 0, 2);

        ta_kv_reduce<<<dim3(8, NHEAD, BATCH), 256>>>(qkvh, qkvl, kv, ks);
        ta_attn_apply<<<dim3(LSEQ/32, BATCH), 256>>>(qkvh, qkvl, kv, ks, ah, al);

        ta_gemm_bf16<<<g256, 256, GEMM_SMEM>>>(ah, al, owh, owl,
                                               bo + l*HID, bo + l*HID, bo + l*HID,
                                               zh, zl, NTOK, HID, HID, 0, 0);
        ta_ln2<<<NTOK/8, dim3(32,8)>>>(zh, zl, ln1s + l*HID, ln1b + l*HID, xh, xl);

        ta_gemm_bf16<<<gff, 256, GEMM_SMEM>>>(xh, xl, w1h, w1l,
                                              b1 + l*FFD, b1 + l*FFD, b1 + l*FFD,
                                              fh, fl, NTOK, HID, FFD, 2, 0);
        ta_gemm_bf16<<<g256, 256, GEMM_SMEM>>>(fh, fl, w2h, w2l,
                                               b2 + l*HID, b2 + l*HID, b2 + l*HID,
                                               zh, zl, NTOK, FFD, HID, 0, 0);
        ta_ln2<<<NTOK/8, dim3(32,8)>>>(zh, zl, ln2s + l*HID, ln2b + l*HID, xh, xl);
    }

    ta_final<<<1, 512>>>(xh, xl, qpW, qpb, (float*)d_out);
}

// round 6
// speedup vs baseline: 2.3021x; 1.0155x over previous
#include <cuda_runtime.h>
#include <cuda_bf16.h>
#include <cstdint>

// ---------------- problem constants ----------------
#define BATCH 16
#define TLEN  4095
#define LSEQ  4096          // TLEN + 1
#define NTOK  (BATCH*LSEQ)  // 65536
#define OBSD  128
#define HID   256
#define NHEAD 8
#define DHEAD 32
#define FFD   1024
#define NLAY  4
#define QKVW  (3*HID)       // 768
#define KEPS  1e-3f
#define LNEPS 1e-6f

typedef __nv_bfloat16 bf16;

// ---------------- device scratch ----------------
__device__ bf16 g_xh [(size_t)NTOK*HID];    __device__ bf16 g_xl [(size_t)NTOK*HID];
__device__ bf16 g_qkvh[(size_t)NTOK*QKVW];  __device__ bf16 g_qkvl[(size_t)NTOK*QKVW];
__device__ bf16 g_ah [(size_t)NTOK*HID];    __device__ bf16 g_al [(size_t)NTOK*HID];
__device__ bf16 g_zh [(size_t)NTOK*HID];    __device__ bf16 g_zl [(size_t)NTOK*HID];
__device__ bf16 g_fh [(size_t)NTOK*FFD];    __device__ bf16 g_fl [(size_t)NTOK*FFD];
__device__ bf16 g_insh[(size_t)(BATCH*TLEN)*OBSD];
__device__ bf16 g_insl[(size_t)(BATCH*TLEN)*OBSD];
__device__ float g_kv  [BATCH*NHEAD*DHEAD*DHEAD];
__device__ float g_ksum[BATCH*NHEAD*DHEAD];
// per-batch effective O weights: WeffT[b][dd][h*32+m], bf16 hi/lo
__device__ bf16 g_weffh[BATCH*HID*HID];
__device__ bf16 g_weffl[BATCH*HID*HID];

// transposed bf16 hi/lo weights (WT[N][K] layout)
#define WT_EMB_SZ   (HID*OBSD)
#define WT_LAYER_SZ (4*HID*HID + 2*HID*FFD)
#define WT_TOTAL    (WT_EMB_SZ + NLAY*WT_LAYER_SZ)
__device__ bf16 g_wth[WT_TOTAL];
__device__ bf16 g_wtl[WT_TOTAL];

static inline int cdiv(int a, int b) { return (a + b - 1) / b; }

// ---------------- helpers ----------------
__device__ __forceinline__ uint32_t smem_u32(const void* p) {
    uint32_t a;
    asm("{ .reg .u64 t; cvta.to.shared.u64 t, %1; cvt.u32.u64 %0, t; }" : "=r"(a) : "l"(p));
    return a;
}
__device__ __forceinline__ float hl(const bf16* H, const bf16* L, size_t i) {
    return __bfloat162float(H[i]) + __bfloat162float(L[i]);
}
__device__ __forceinline__ void sphl(float f, bf16* H, bf16* L, size_t i) {
    bf16 h = __float2bfloat16(f);
    H[i] = h;
    L[i] = __float2bfloat16(f - __bfloat162float(h));
}

#define LDSM4(r, addr)                                                     \
    asm volatile("ldmatrix.sync.aligned.m8n8.x4.shared.b16 "               \
                 "{%0,%1,%2,%3}, [%4];"                                    \
                 : "=r"((r)[0]), "=r"((r)[1]), "=r"((r)[2]), "=r"((r)[3])  \
                 : "r"(addr))

#define MMA_BF16(d, a, b0, b1)                                             \
    asm volatile("mma.sync.aligned.m16n8k16.row.col.f32.bf16.bf16.f32 "    \
                 "{%0,%1,%2,%3},{%4,%5,%6,%7},{%8,%9},{%0,%1,%2,%3};"      \
                 : "+f"((d)[0]), "+f"((d)[1]), "+f"((d)[2]), "+f"((d)[3])  \
                 : "r"((a)[0]), "r"((a)[1]), "r"((a)[2]), "r"((a)[3]),     \
                   "r"(b0), "r"(b1))

__device__ __forceinline__ void cpa16(uint32_t dst, const void* src, int sz) {
    asm volatile("cp.async.cg.shared.global [%0], [%1], 16, %2;"
                 :: "r"(dst), "l"(__cvta_generic_to_global(src)), "r"(sz));
}

// ---------------- single-launch weight conversion ----------------
__global__ void ta_wconv_all(const float* __restrict__ embW,
                             const float* __restrict__ Wq, const float* __restrict__ Wk,
                             const float* __restrict__ Wv, const float* __restrict__ Wo,
                             const float* __restrict__ W1, const float* __restrict__ W2,
                             bf16* __restrict__ hi, bf16* __restrict__ lo) {
    const int seg = blockIdx.y;
    const float* src;
    int K, N;
    size_t dst;
    if (seg == 0) {
        src = embW; K = OBSD; N = HID; dst = 0;
    } else {
        const int l = (seg - 1) / 6, m = (seg - 1) % 6;
        const size_t base = WT_EMB_SZ + (size_t)l * WT_LAYER_SZ;
        switch (m) {
            case 0: src = Wq + (size_t)l*HID*HID; K = HID; N = HID; dst = base;          break;
            case 1: src = Wk + (size_t)l*HID*HID; K = HID; N = HID; dst = base + 65536;  break;
            case 2: src = Wv + (size_t)l*HID*HID; K = HID; N = HID; dst = base + 131072; break;
            case 3: src = Wo + (size_t)l*HID*HID; K = HID; N = HID; dst = base + 196608; break;
            case 4: src = W1 + (size_t)l*HID*FFD; K = HID; N = FFD; dst = base + 262144; break;
            default:src = W2 + (size_t)l*FFD*HID; K = FFD; N = HID; dst = base + 524288; break;
        }
    }
    int i = blockIdx.x * 256 + threadIdx.x;
    if (i >= N * K) return;
    int n = i / K, k = i - n * K;
    float w = src[(size_t)k * N + n];
    bf16 h = __float2bfloat16(w);
    hi[dst + i] = h;
    lo[dst + i] = __float2bfloat16(w - __bfloat162float(h));
}

__global__ void ta_split(const float* __restrict__ src,
                         bf16* __restrict__ H, bf16* __restrict__ L, int n) {
    int i = blockIdx.x * 256 + threadIdx.x;
    if (i < n) sphl(src[i], H, L, i);
}

__global__ void ta_init_hidden(const float* __restrict__ hs,
                               const unsigned char* __restrict__ resets,
                               bf16* __restrict__ XH, bf16* __restrict__ XL) {
    int b = blockIdx.x, c = threadIdx.x;
    float v = resets[b] ? 0.f : hs[b*HID + c];
    sphl(v, XH, XL, (size_t)b*LSEQ*HID + c);
}

// ---------------- bf16 hi/lo 3-pass MMA GEMM (3-stage, swizzled) ----------------
// flags: bit0 = embRemap, bit1 = qkvMode, bit2 = batchedB (B += (rowBase>>12)*HID*HID)
__global__ __launch_bounds__(256, 2)
void ta_gemm_bf16(const bf16* __restrict__ Ah, const bf16* __restrict__ Al,
                  const bf16* __restrict__ Bh, const bf16* __restrict__ Bl,
                  const float* __restrict__ bias0, const float* __restrict__ bias1,
                  const float* __restrict__ bias2,
                  bf16* __restrict__ Ch, bf16* __restrict__ Cl,
                  int M, int K, int N, int epi, int flags) {
    extern __shared__ char smem[];
    const uint32_t smu = smem_u32(smem);

    const int tid  = threadIdx.x;
    const int wid  = tid >> 5;
    const int lane = tid & 31;
    const int wr   = wid >> 2;
    const int wc   = wid & 3;
    const int rowBase = blockIdx.y * 128;
    const int colBase = blockIdx.x * 128;

    if (flags & 4) {
        const size_t boff = (size_t)(rowBase >> 12) * HID * HID;
        Bh += boff;  Bl += boff;
    }

    const int r  = tid >> 2;
    const int ch = tid & 3;
    const uint32_t stOff  = (uint32_t)(r * 64 + ((ch ^ ((r >> 1) & 3)) << 4));
    const uint32_t stOff2 = (uint32_t)((r + 64) * 64 + ((ch ^ (((r + 64) >> 1) & 3)) << 4));

    const int r15 = lane & 15;
    const int hi_ = lane >> 4;
    const int sw  = (r15 >> 1) & 3;
    const uint32_t rowB  = (uint32_t)(r15 * 64);
    const uint32_t co0   = rowB + (uint32_t)(((hi_    ) ^ sw) << 4);
    const uint32_t co1   = rowB + (uint32_t)(((2 + hi_) ^ sw) << 4);
    const uint32_t aWarp = (uint32_t)(wr * 4096);
    const uint32_t bWarp = (uint32_t)(wc * 2048);

    float acc[4][4][4] = {};

    auto load_stage = [&](int st, int kt) {
        const uint32_t sb = smu + (uint32_t)st * 32768u;
        const int kOff = kt * 32 + ch * 8;
        {
            const int grow = rowBase + r;
            const int sz = (grow < M) ? 16 : 0;
            const size_t asrc = (size_t)(sz ? grow : 0) * K + kOff;
            cpa16(sb + stOff,          Ah + asrc, sz);
            cpa16(sb + 8192u + stOff,  Al + asrc, sz);
            const size_t bsrc = (size_t)(colBase + r) * K + kOff;
            cpa16(sb + 16384u + stOff, Bh + bsrc, 16);
            cpa16(sb + 24576u + stOff, Bl + bsrc, 16);
        }
        {
            const int grow = rowBase + r + 64;
            const int sz = (grow < M) ? 16 : 0;
            const size_t asrc = (size_t)(sz ? grow : 0) * K + kOff;
            cpa16(sb + stOff2,          Ah + asrc, sz);
            cpa16(sb + 8192u + stOff2,  Al + asrc, sz);
            const size_t bsrc = (size_t)(colBase + r + 64) * K + kOff;
            cpa16(sb + 16384u + stOff2, Bh + bsrc, 16);
            cpa16(sb + 24576u + stOff2, Bl + bsrc, 16);
        }
        asm volatile("cp.async.commit_group;");
    };

    auto compute = [&](int st) {
        const uint32_t sb  = smu + (uint32_t)st * 32768u;
        const uint32_t aHB = sb + aWarp;
        const uint32_t aLB = aHB + 8192u;
        const uint32_t bHB = sb + 16384u + bWarp;
        const uint32_t bLB = bHB + 8192u;
        #pragma unroll
        for (int ks = 0; ks < 2; ks++) {
            const uint32_t co = ks ? co1 : co0;
            uint32_t bH[2][4], bL[2][4];
            LDSM4(bH[0], bHB + co);
            LDSM4(bH[1], bHB + 1024u + co);
            LDSM4(bL[0], bLB + co);
            LDSM4(bL[1], bLB + 1024u + co);
            uint32_t a[4][4];
            #pragma unroll
            for (int mi = 0; mi < 4; mi++) LDSM4(a[mi], aHB + mi * 1024u + co);
            #pragma unroll
            for (int mi = 0; mi < 4; mi++)
                #pragma unroll
                for (int nt = 0; nt < 4; nt++) {
                    MMA_BF16(acc[mi][nt], a[mi], bH[nt >> 1][nt & 1], bH[nt >> 1][(nt & 1) + 2]);
                    MMA_BF16(acc[mi][nt], a[mi], bL[nt >> 1][nt & 1], bL[nt >> 1][(nt & 1) + 2]);
                }
            #pragma unroll
            for (int mi = 0; mi < 4; mi++) LDSM4(a[mi], aLB + mi * 1024u + co);
            #pragma unroll
            for (int mi = 0; mi < 4; mi++)
                #pragma unroll
                for (int nt = 0; nt < 4; nt++)
                    MMA_BF16(acc[mi][nt], a[mi], bH[nt >> 1][nt & 1], bH[nt >> 1][(nt & 1) + 2]);
        }
    };

    const int nk = K >> 5;
    load_stage(0, 0);
    load_stage(1, 1);
    int cs = 0, ls = 2;
    for (int kt = 0; kt < nk; kt++) {
        if (kt == nk - 1) asm volatile("cp.async.wait_group 0;");
        else              asm volatile("cp.async.wait_group 1;");
        __syncthreads();
        if (kt + 2 < nk) {
            load_stage(ls, kt + 2);
            ls = (ls == 2) ? 0 : ls + 1;
        }
        compute(cs);
        cs = (cs == 2) ? 0 : cs + 1;
    }

    // ---- epilogue
    const bool embRemap = flags & 1;
    const bool qkvMode  = flags & 2;
    const float* bptr = bias0;
    int ep = epi;
    if (qkvMode) {
        int seg = colBase >> 8;
        bptr = (seg == 0) ? bias0 : (seg == 1) ? bias1 : bias2;
        ep = (seg < 2) ? 1 : 0;
    }
    const int t4 = lane >> 2;
    const int t2 = (lane & 3) << 1;
    #pragma unroll
    for (int mi = 0; mi < 4; mi++) {
        #pragma unroll
        for (int duo = 0; duo < 2; duo++) {
            const int row = rowBase + wr * 64 + mi * 16 + t4 + duo * 8;
            if (row >= M) continue;
            size_t orow = (size_t)row;
            if (embRemap) {
                int b = row / TLEN;
                orow = (size_t)b * LSEQ + 1 + (row - b * TLEN);
            }
            #pragma unroll
            for (int nt = 0; nt < 4; nt++) {
                const int col = colBase + wc * 32 + nt * 8 + t2;
                const int bcol = qkvMode ? (col & 255) : col;
                float c0 = acc[mi][nt][duo * 2 + 0] + bptr[bcol];
                float c1 = acc[mi][nt][duo * 2 + 1] + bptr[bcol + 1];
                if (ep == 1)      { c0 = fmaxf(c0, 0.f) + KEPS; c1 = fmaxf(c1, 0.f) + KEPS; }
                else if (ep == 2) { c0 = fmaxf(c0, 0.f);        c1 = fmaxf(c1, 0.f); }
                bf16 h0 = __float2bfloat16(c0), h1 = __float2bfloat16(c1);
                bf16 l0 = __float2bfloat16(c0 - __bfloat162float(h0));
                bf16 l1 = __float2bfloat16(c1 - __bfloat162float(h1));
                uint32_t hp = (uint32_t)*(uint16_t*)&h0 | ((uint32_t)*(uint16_t*)&h1 << 16);
                uint32_t lp = (uint32_t)*(uint16_t*)&l0 | ((uint32_t)*(uint16_t*)&l1 << 16);
                *(uint32_t*)(Ch + orow * N + col) = hp;
                *(uint32_t*)(Cl + orow * N + col) = lp;
            }
        }
    }
}

// ---------------- zero kv/ksum ----------------
__global__ void ta_zero_kv(float* __restrict__ KV, float* __restrict__ KS) {
    int i = blockIdx.x * 256 + threadIdx.x;
    if (i < BATCH*NHEAD*DHEAD*DHEAD) KV[i] = 0.f;
    if (i < BATCH*NHEAD*DHEAD)       KS[i] = 0.f;
}

// ---------------- kv = sum_l kp (x) v ; ksum = sum_l kp ----------------
__global__ void ta_kv_reduce(const bf16* __restrict__ QKVh, const bf16* __restrict__ QKVl,
                             float* __restrict__ KV, float* __restrict__ KS) {
    const int s = blockIdx.x, h = blockIdx.y, b = blockIdx.z;
    const int CH = LSEQ / 8;
    const int tid = threadIdx.x;
    const int w = tid >> 5, lane = tid & 31;

    __shared__ float kps[8][32];
    __shared__ float vs [8][32];

    float acc[4] = {0.f, 0.f, 0.f, 0.f};
    float ksa = 0.f;
    const size_t rowBase = (size_t)b * LSEQ + (size_t)s * CH;

    for (int l0 = 0; l0 < CH; l0 += 8) {
        size_t rbase = (rowBase + l0 + w) * QKVW + h * DHEAD + lane;
        kps[w][lane] = hl(QKVh, QKVl, rbase + HID);
        vs [w][lane] = hl(QKVh, QKVl, rbase + 2*HID);
        __syncthreads();
        #pragma unroll
        for (int q = 0; q < 8; q++) {
            float vd = vs[q][lane];
            #pragma unroll
            for (int j = 0; j < 4; j++)
                acc[j] += kps[q][w + 8*j] * vd;
            if (tid < 32) ksa += kps[q][lane];
        }
        __syncthreads();
    }
    const int bh = b * NHEAD + h;
    #pragma unroll
    for (int j = 0; j < 4; j++)
        atomicAdd(&KV[bh*1024 + (w + 8*j)*32 + lane], acc[j]);
    if (tid < 32) atomicAdd(&KS[bh*32 + lane], ksa);
}

// ---------------- WeffT[b][dd][(h,m)] = sum_d' kv[b,h][m][d'] * Wo[h][d'][dd] ----
// grid (NHEAD, BATCH), 256 threads (thread = dd)
__global__ void ta_weff(const float* __restrict__ KV, const float* __restrict__ Wo,
                        bf16* __restrict__ WH, bf16* __restrict__ WL) {
    const int h = blockIdx.x, b = blockIdx.y;
    const int tid = threadIdx.x;   // dd
    __shared__ float kvs[DHEAD*DHEAD];
    for (int i = tid; i < DHEAD*DHEAD; i += 256)
        kvs[i] = KV[(b*NHEAD + h)*1024 + i];
    __syncthreads();

    float wcol[DHEAD];
    #pragma unroll
    for (int d = 0; d < DHEAD; d++)
        wcol[d] = Wo[((size_t)h*DHEAD + d)*HID + tid];

    for (int m = 0; m < DHEAD; m++) {
        const float4* k4 = (const float4*)&kvs[m*DHEAD];
        float a0 = 0.f;
        #pragma unroll
        for (int q = 0; q < 8; q++) {
            float4 kk = k4[q];
            a0 += kk.x*wcol[4*q] + kk.y*wcol[4*q+1] + kk.z*wcol[4*q+2] + kk.w*wcol[4*q+3];
        }
        size_t idx = ((size_t)b*HID + tid)*HID + h*DHEAD + m;
        bf16 hh = __float2bfloat16(a0);
        WH[idx] = hh;
        WL[idx] = __float2bfloat16(a0 - __bfloat162float(hh));
    }
}

// ---------------- qp' = qp / (qp . ksum) ----------------
// grid (LSEQ/32, BATCH), 256 threads
__global__ void ta_qpscale(const bf16* __restrict__ QKVh, const bf16* __restrict__ QKVl,
                           const float* __restrict__ KS,
                           bf16* __restrict__ AH, bf16* __restrict__ AL) {
    __shared__ float kss[HID];
    const int b = blockIdx.y;
    const int tokBase = blockIdx.x * 32;
    const int tid = threadIdx.x;
    kss[tid] = KS[b * HID + tid];
    __syncthreads();

    const int w = tid >> 5, lane = tid & 31;
    const int h = lane >> 2, tk = lane & 3;
    const int tok = tokBase + w * 4 + tk;
    const size_t qrow = ((size_t)b * LSEQ + tok) * QKVW + h * DHEAD;
    const size_t arow = ((size_t)b * LSEQ + tok) * HID  + h * DHEAD;

    float qv[DHEAD];
    float den = 0.f;
    #pragma unroll
    for (int m = 0; m < DHEAD; m++) {
        qv[m] = hl(QKVh, QKVl, qrow + m);
        den += qv[m] * kss[h*DHEAD + m];
    }
    const float inv = 1.f / den;
    #pragma unroll
    for (int m = 0; m < DHEAD; m++)
        sphl(qv[m] * inv, AH, AL, arow + m);
}

// ---------------- X = LN(2*Z)*scale + bias ----------------
__global__ void ta_ln2(const bf16* __restrict__ ZH, const bf16* __restrict__ ZL,
                       const float* __restrict__ sc, const float* __restrict__ bi,
                       bf16* __restrict__ XH, bf16* __restrict__ XL) {
    const int row  = blockIdx.x * 8 + threadIdx.y;
    const int lane = threadIdx.x;
    const size_t base = (size_t)row * HID;

    float v[8];
    float sum = 0.f;
    #pragma unroll
    for (int j = 0; j < 8; j++) { v[j] = 2.f * hl(ZH, ZL, base + lane + j*32); sum += v[j]; }
    #pragma unroll
    for (int o = 16; o; o >>= 1) sum += __shfl_xor_sync(0xffffffffu, sum, o);
    const float mean = sum * (1.f / HID);

    float vs = 0.f;
    #pragma unroll
    for (int j = 0; j < 8; j++) { float d = v[j] - mean; vs += d * d; }
    #pragma unroll
    for (int o = 16; o; o >>= 1) vs += __shfl_xor_sync(0xffffffffu, vs, o);
    const float rr = rsqrtf(vs * (1.f / HID) + LNEPS);

    #pragma unroll
    for (int j = 0; j < 8; j++) {
        int c = lane + j*32;
        sphl((v[j] - mean) * rr * sc[c] + bi[c], XH, XL, base + c);
    }
}

// ---------------- final readout ----------------
__global__ void ta_final(const bf16* __restrict__ XH, const bf16* __restrict__ XL,
                         const float* __restrict__ qpW, const float* __restrict__ qpb,
                         float* __restrict__ out) {
    const int tid = threadIdx.x;   // 512
    for (int i = tid; i < BATCH*HID; i += 512) {
        int b = i >> 8, c = i & 255;
        out[i] = hl(XH, XL, (size_t)b * LSEQ * HID + c);
    }
    const int b = tid >> 5, j = tid & 31;
    const size_t xr = (size_t)b * LSEQ * HID;
    float s = qpb[j];
    #pragma unroll 8
    for (int c = 0; c < HID; c++) s += hl(XH, XL, xr + c) * qpW[c*32 + j];
    out[BATCH*HID + tid] = s;
}

// ---------------- launcher ----------------
extern "C" void kernel_launch(void* const* d_in, const int* in_sizes, int n_in,
                              void* d_out, int out_size) {
    const float* hidden = (const float*)d_in[0];
    const float* ins    = (const float*)d_in[1];
    const unsigned char* resets = (const unsigned char*)d_in[2];
    const float* embW = (const float*)d_in[3];
    const float* embb = (const float*)d_in[4];
    const float* Wq = (const float*)d_in[5];
    const float* bq = (const float*)d_in[6];
    const float* Wk = (const float*)d_in[7];
    const float* bk = (const float*)d_in[8];
    const float* Wv = (const float*)d_in[9];
    const float* bv = (const float*)d_in[10];
    const float* Wo = (const float*)d_in[11];
    const float* bo = (const float*)d_in[12];
    const float* ln1s = (const float*)d_in[13];
    const float* ln1b = (const float*)d_in[14];
    const float* W1 = (const float*)d_in[15];
    const float* b1 = (const float*)d_in[16];
    const float* W2 = (const float*)d_in[17];
    const float* b2 = (const float*)d_in[18];
    const float* ln2s = (const float*)d_in[19];
    const float* ln2b = (const float*)d_in[20];
    const float* qpW = (const float*)d_in[21];
    const float* qpb = (const float*)d_in[22];

    bf16 *xh,*xl,*qkvh,*qkvl,*ah,*al,*zh,*zl,*fh,*fl,*insh,*insl,*wth,*wtl,*weh,*wel;
    float *kv, *ks;
    cudaGetSymbolAddress((void**)&xh,   g_xh);   cudaGetSymbolAddress((void**)&xl,   g_xl);
    cudaGetSymbolAddress((void**)&qkvh, g_qkvh); cudaGetSymbolAddress((void**)&qkvl, g_qkvl);
    cudaGetSymbolAddress((void**)&ah,   g_ah);   cudaGetSymbolAddress((void**)&al,   g_al);
    cudaGetSymbolAddress((void**)&zh,   g_zh);   cudaGetSymbolAddress((void**)&zl,   g_zl);
    cudaGetSymbolAddress((void**)&fh,   g_fh);   cudaGetSymbolAddress((void**)&fl,   g_fl);
    cudaGetSymbolAddress((void**)&insh, g_insh); cudaGetSymbolAddress((void**)&insl, g_insl);
    cudaGetSymbolAddress((void**)&wth,  g_wth);  cudaGetSymbolAddress((void**)&wtl,  g_wtl);
    cudaGetSymbolAddress((void**)&weh,  g_weffh);cudaGetSymbolAddress((void**)&wel,  g_weffl);
    cudaGetSymbolAddress((void**)&kv,   g_kv);   cudaGetSymbolAddress((void**)&ks,   g_ksum);

    const int GEMM_SMEM = 98304;   // 3 stages x 32KB
    cudaFuncSetAttribute(ta_gemm_bf16, cudaFuncAttributeMaxDynamicSharedMemorySize, GEMM_SMEM);

    ta_wconv_all<<<dim3(1024, 25), 256>>>(embW, Wq, Wk, Wv, Wo, W1, W2, wth, wtl);
    {
        int n = BATCH*TLEN*OBSD;
        ta_split<<<cdiv(n,256), 256>>>(ins, insh, insl, n);
    }
    ta_init_hidden<<<BATCH, HID>>>(hidden, resets, xh, xl);
    {
        int M = BATCH * TLEN;
        ta_gemm_bf16<<<dim3(HID/128, cdiv(M,128)), 256, GEMM_SMEM>>>(
            insh, insl, wth, wtl, embb, embb, embb, xh, xl, M, OBSD, HID, 0, 1);
    }

    const dim3 gqkv(QKVW/128, NTOK/128);  // (6, 512)
    const dim3 g256(HID/128,  NTOK/128);  // (2, 512)
    const dim3 gff (FFD/128,  NTOK/128);  // (8, 512)

    for (int l = 0; l < NLAY; l++) {
        size_t base = WT_EMB_SZ + (size_t)l * WT_LAYER_SZ;
        const bf16 *qkvwh = wth + base,          *qkvwl = wtl + base;
        const bf16 *w1h   = wth + base + 262144, *w1l   = wtl + base + 262144;
        const bf16 *w2h   = wth + base + 524288, *w2l   = wtl + base + 524288;

        ta_zero_kv<<<cdiv(BATCH*NHEAD*DHEAD*DHEAD, 256), 256>>>(kv, ks);
        ta_gemm_bf16<<<gqkv, 256, GEMM_SMEM>>>(xh, xl, qkvwh, qkvwl,
                                               bq + l*HID, bk + l*HID, bv + l*HID,
                                               qkvh, qkvl, NTOK, HID, QKVW, 0, 2);

        ta_kv_reduce<<<dim3(8, NHEAD, BATCH), 256>>>(qkvh, qkvl, kv, ks);
        ta_weff<<<dim3(NHEAD, BATCH), 256>>>(kv, Wo + (size_t)l*HID*HID, weh, wel);
        ta_qpscale<<<dim3(LSEQ/32, BATCH), 256>>>(qkvh, qkvl, ks, ah, al);

        // o = qp' @ Weff[b] + bo  (batched B via flag bit2)
        ta_gemm_bf16<<<g256, 256, GEMM_SMEM>>>(ah, al, weh, wel,
                                               bo + l*HID, bo + l*HID, bo + l*HID,
                                               zh, zl, NTOK, HID, HID, 0, 4);
        ta_ln2<<<NTOK/8, dim3(32,8)>>>(zh, zl, ln1s + l*HID, ln1b + l*HID, xh, xl);

        ta_gemm_bf16<<<gff, 256, GEMM_SMEM>>>(xh, xl, w1h, w1l,
                                              b1 + l*FFD, b1 + l*FFD, b1 + l*FFD,
                                              fh, fl, NTOK, HID, FFD, 2, 0);
        ta_gemm_bf16<<<g256, 256, GEMM_SMEM>>>(fh, fl, w2h, w2l,
                                               b2 + l*HID, b2 + l*HID, b2 + l*HID,
                                               zh, zl, NTOK, FFD, HID, 0, 0);
        ta_ln2<<<NTOK/8, dim3(32,8)>>>(zh, zl, ln2s + l*HID, ln2b + l*HID, xh, xl);
    }

    ta_final<<<1, 512>>>(xh, xl, qpW, qpb, (float*)d_out);
}